// round 1
// baseline (speedup 1.0000x reference)
#include <cuda_runtime.h>
#include <cuda_bf16.h>
#include <math.h>

// ---------------------------------------------------------------------------
// Problem constants
// ---------------------------------------------------------------------------
#define BB     4
#define TT     2048
#define DM     256
#define DFF    1024
#define NH     4
#define DK     64
#define BT     (BB*TT)          // 8192 rows

// ---------------------------------------------------------------------------
// Scratch (device globals: allocation-free per harness rules)
// ---------------------------------------------------------------------------
__device__ float g_h   [BT*DM];
__device__ float g_q   [BT*DM];
__device__ float g_k   [BT*DM];
__device__ float g_v   [BT*DM];
__device__ float g_attn[BT*DM];
__device__ float g_x1  [BT*DM];
__device__ float g_hf  [BT*DM];
__device__ float g_gate[BT*DFF];
__device__ float g_up  [BT*DFF];

// ---------------------------------------------------------------------------
// RMSNorm: one block per row of 256
// ---------------------------------------------------------------------------
__global__ void rmsnorm_kernel(float* __restrict__ out, const float* __restrict__ x,
                               const float* __restrict__ w) {
    int row = blockIdx.x;
    int tid = threadIdx.x;
    float vx = x[row*DM + tid];
    float ss = vx*vx;
    #pragma unroll
    for (int off = 16; off >= 1; off >>= 1) ss += __shfl_xor_sync(0xffffffffu, ss, off);
    __shared__ float ws[8];
    if ((tid & 31) == 0) ws[tid >> 5] = ss;
    __syncthreads();
    float tot = ws[0];
    #pragma unroll
    for (int i = 1; i < 8; ++i) tot += ws[i];
    float rinv = rsqrtf(tot * (1.0f/DM) + 1e-5f);
    out[row*DM + tid] = vx * rinv * w[tid];
}

// ---------------------------------------------------------------------------
// GEMM: C[M,N] = A[M,K] @ Bw[N,K]^T (+ res[M,N] if res != nullptr)
// Tile 128x64, BK=16, 256 threads, 8x4 micro-tile per thread
// ---------------------------------------------------------------------------
#define GBM 128
#define GBN 64
#define GBK 16

__global__ __launch_bounds__(256, 2)
void gemm_kernel(float* __restrict__ C, const float* __restrict__ A,
                 const float* __restrict__ Bw, const float* __restrict__ res,
                 int M, int N, int K) {
    __shared__ float As[GBM][GBK+1];
    __shared__ float Bs[GBN][GBK+1];
    int tid = threadIdx.x;
    int tx = tid & 15, ty = tid >> 4;
    int row0 = blockIdx.y * GBM;
    int col0 = blockIdx.x * GBN;

    float acc[8][4];
    #pragma unroll
    for (int r = 0; r < 8; ++r)
        #pragma unroll
        for (int c = 0; c < 4; ++c) acc[r][c] = 0.f;

    for (int k0 = 0; k0 < K; k0 += GBK) {
        #pragma unroll
        for (int l = 0; l < 8; ++l) {
            int e = l*256 + tid;
            int i = e >> 4, k = e & 15;
            As[i][k] = A[(size_t)(row0+i)*K + k0 + k];
        }
        #pragma unroll
        for (int l = 0; l < 4; ++l) {
            int e = l*256 + tid;
            int i = e >> 4, k = e & 15;
            Bs[i][k] = Bw[(size_t)(col0+i)*K + k0 + k];
        }
        __syncthreads();
        #pragma unroll
        for (int k = 0; k < GBK; ++k) {
            float a[8], b[4];
            #pragma unroll
            for (int r = 0; r < 8; ++r) a[r] = As[ty*8+r][k];
            #pragma unroll
            for (int c = 0; c < 4; ++c) b[c] = Bs[tx*4+c][k];
            #pragma unroll
            for (int r = 0; r < 8; ++r)
                #pragma unroll
                for (int c = 0; c < 4; ++c) acc[r][c] += a[r]*b[c];
        }
        __syncthreads();
    }
    #pragma unroll
    for (int r = 0; r < 8; ++r) {
        int m = row0 + ty*8 + r;
        #pragma unroll
        for (int c = 0; c < 4; ++c) {
            int n = col0 + tx*4 + c;
            float vv = acc[r][c];
            if (res) vv += res[(size_t)m*N + n];
            C[(size_t)m*N + n] = vv;
        }
    }
}

// ---------------------------------------------------------------------------
// Flash attention: block = (qtile 64 rows, one (b,h)); causal; online softmax
// 256 threads, 4x4 micro-tile per thread on 64x64 tiles
// ---------------------------------------------------------------------------
__global__ __launch_bounds__(256, 3)
void attn_kernel(float* __restrict__ out, const float* __restrict__ q,
                 const float* __restrict__ k, const float* __restrict__ v) {
    extern __shared__ float sm[];
    float* Qs = sm;                 // 64*64
    float* Ks = Qs + 64*64;         // 64*65 (padded)
    float* Vs = Ks + 64*65;         // 64*64
    float* Ps = Vs + 64*64;         // 64*65 (padded)

    int tid = threadIdx.x;
    int tx = tid & 15, ty = tid >> 4;
    int qtile = blockIdx.x;
    int bh = blockIdx.y;
    int b = bh >> 2, h = bh & 3;
    int q0 = qtile * 64;
    size_t base = ((size_t)b * TT) * DM + (size_t)h * DK;

    // load Q tile
    #pragma unroll
    for (int l = 0; l < 16; ++l) {
        int e = l*256 + tid;
        int i = e >> 6, d = e & 63;
        Qs[i*64 + d] = q[base + (size_t)(q0+i)*DM + d];
    }

    float m_i[4], l_i[4], o[4][4];
    #pragma unroll
    for (int r = 0; r < 4; ++r) {
        m_i[r] = -1e30f; l_i[r] = 0.f;
        #pragma unroll
        for (int c = 0; c < 4; ++c) o[r][c] = 0.f;
    }
    const float scale = 0.125f;   // 1/sqrt(64)

    for (int jt = 0; jt <= qtile; ++jt) {
        int k0 = jt * 64;
        __syncthreads();  // prior-iter Ps/Vs reads done before overwrite
        #pragma unroll
        for (int l = 0; l < 16; ++l) {
            int e = l*256 + tid;
            int i = e >> 6, d = e & 63;
            Ks[i*65 + d] = k[base + (size_t)(k0+i)*DM + d];
            Vs[i*64 + d] = v[base + (size_t)(k0+i)*DM + d];
        }
        __syncthreads();

        // S = Q @ K^T
        float s[4][4];
        #pragma unroll
        for (int r = 0; r < 4; ++r)
            #pragma unroll
            for (int c = 0; c < 4; ++c) s[r][c] = 0.f;
        #pragma unroll 8
        for (int d = 0; d < 64; ++d) {
            float qa[4], kb[4];
            #pragma unroll
            for (int r = 0; r < 4; ++r) qa[r] = Qs[(ty*4+r)*64 + d];
            #pragma unroll
            for (int c = 0; c < 4; ++c) kb[c] = Ks[(tx*4+c)*65 + d];
            #pragma unroll
            for (int r = 0; r < 4; ++r)
                #pragma unroll
                for (int c = 0; c < 4; ++c) s[r][c] += qa[r]*kb[c];
        }
        // scale + causal mask
        #pragma unroll
        for (int r = 0; r < 4; ++r)
            #pragma unroll
            for (int c = 0; c < 4; ++c) {
                int qi = q0 + ty*4 + r, kj = k0 + tx*4 + c;
                s[r][c] = (kj <= qi) ? s[r][c]*scale : -1e30f;
            }
        // row reductions across the 16-lane tx groups
        float mnew[4], alpha[4];
        #pragma unroll
        for (int r = 0; r < 4; ++r) {
            float mx = fmaxf(fmaxf(s[r][0], s[r][1]), fmaxf(s[r][2], s[r][3]));
            #pragma unroll
            for (int off = 8; off >= 1; off >>= 1)
                mx = fmaxf(mx, __shfl_xor_sync(0xffffffffu, mx, off));
            mnew[r] = fmaxf(m_i[r], mx);
            alpha[r] = __expf(m_i[r] - mnew[r]);
            m_i[r] = mnew[r];
        }
        #pragma unroll
        for (int r = 0; r < 4; ++r) {
            float rs = 0.f;
            #pragma unroll
            for (int c = 0; c < 4; ++c) {
                float p = __expf(s[r][c] - mnew[r]);
                s[r][c] = p; rs += p;
            }
            #pragma unroll
            for (int off = 8; off >= 1; off >>= 1)
                rs += __shfl_xor_sync(0xffffffffu, rs, off);
            l_i[r] = l_i[r]*alpha[r] + rs;
        }
        // stage P
        #pragma unroll
        for (int r = 0; r < 4; ++r)
            #pragma unroll
            for (int c = 0; c < 4; ++c)
                Ps[(ty*4+r)*65 + tx*4+c] = s[r][c];
        __syncthreads();
        // O = O*alpha + P @ V
        #pragma unroll
        for (int r = 0; r < 4; ++r)
            #pragma unroll
            for (int c = 0; c < 4; ++c) o[r][c] *= alpha[r];
        #pragma unroll 8
        for (int kk = 0; kk < 64; ++kk) {
            float pa[4], vb[4];
            #pragma unroll
            for (int r = 0; r < 4; ++r) pa[r] = Ps[(ty*4+r)*65 + kk];
            #pragma unroll
            for (int c = 0; c < 4; ++c) vb[c] = Vs[kk*64 + tx*4+c];
            #pragma unroll
            for (int r = 0; r < 4; ++r)
                #pragma unroll
                for (int c = 0; c < 4; ++c) o[r][c] += pa[r]*vb[c];
        }
    }

    #pragma unroll
    for (int r = 0; r < 4; ++r) {
        float inv = 1.f / l_i[r];
        int qi = q0 + ty*4 + r;
        #pragma unroll
        for (int c = 0; c < 4; ++c)
            out[base + (size_t)qi*DM + tx*4 + c] = o[r][c]*inv;
    }
}

// ---------------------------------------------------------------------------
// SiLU(gate) * up, in place into gate buffer
// ---------------------------------------------------------------------------
__global__ void silu_mul_kernel(float* __restrict__ g, const float* __restrict__ u, int n) {
    int i = blockIdx.x*blockDim.x + threadIdx.x;
    int stride = gridDim.x*blockDim.x;
    for (; i < n; i += stride) {
        float gv = g[i];
        float s = gv / (1.f + __expf(-gv));
        g[i] = s * u[i];
    }
}

// ---------------------------------------------------------------------------
// Launch
// ---------------------------------------------------------------------------
extern "C" void kernel_launch(void* const* d_in, const int* in_sizes, int n_in,
                              void* d_out, int out_size) {
    const float* x        = (const float*)d_in[0];
    // d_in[1] = causal_mask (unused; causality computed analytically)
    const float* rms_attn = (const float*)d_in[2];
    const float* wq       = (const float*)d_in[3];
    const float* wk       = (const float*)d_in[4];
    const float* wv       = (const float*)d_in[5];
    const float* wo       = (const float*)d_in[6];
    const float* rms_ffn  = (const float*)d_in[7];
    const float* w_gate   = (const float*)d_in[8];
    const float* w_up     = (const float*)d_in[9];
    const float* w_down   = (const float*)d_in[10];
    float* out = (float*)d_out;

    float *h, *q, *k, *v, *attn, *x1, *hf, *gate, *up;
    cudaGetSymbolAddress((void**)&h,    g_h);
    cudaGetSymbolAddress((void**)&q,    g_q);
    cudaGetSymbolAddress((void**)&k,    g_k);
    cudaGetSymbolAddress((void**)&v,    g_v);
    cudaGetSymbolAddress((void**)&attn, g_attn);
    cudaGetSymbolAddress((void**)&x1,   g_x1);
    cudaGetSymbolAddress((void**)&hf,   g_hf);
    cudaGetSymbolAddress((void**)&gate, g_gate);
    cudaGetSymbolAddress((void**)&up,   g_up);

    // attention needs >48KB dynamic smem
    static const size_t attn_smem = (size_t)(64*64 + 64*65 + 64*64 + 64*65) * sizeof(float);
    cudaFuncSetAttribute(attn_kernel, cudaFuncAttributeMaxDynamicSharedMemorySize, (int)attn_smem);

    // 1. h = rmsnorm(x)
    rmsnorm_kernel<<<BT, 256>>>(h, x, rms_attn);

    // 2. q,k,v projections
    dim3 gQKV(DM/GBN, BT/GBM);
    gemm_kernel<<<gQKV, 256>>>(q, h, wq, nullptr, BT, DM, DM);
    gemm_kernel<<<gQKV, 256>>>(k, h, wk, nullptr, BT, DM, DM);
    gemm_kernel<<<gQKV, 256>>>(v, h, wv, nullptr, BT, DM, DM);

    // 3. attention
    dim3 gAttn(TT/64, BB*NH);
    attn_kernel<<<gAttn, 256, attn_smem>>>(attn, q, k, v);

    // 4. x1 = x + attn @ wo^T
    gemm_kernel<<<gQKV, 256>>>(x1, attn, wo, x, BT, DM, DM);

    // 5. hf = rmsnorm(x1)
    rmsnorm_kernel<<<BT, 256>>>(hf, x1, rms_ffn);

    // 6. gate/up
    dim3 gFF(DFF/GBN, BT/GBM);
    gemm_kernel<<<gFF, 256>>>(gate, hf, w_gate, nullptr, BT, DFF, DM);
    gemm_kernel<<<gFF, 256>>>(up,   hf, w_up,   nullptr, BT, DFF, DM);

    // 7. gate = silu(gate)*up
    silu_mul_kernel<<<4096, 256>>>(gate, up, BT*DFF);

    // 8. out = x1 + gate @ w_down^T
    gemm_kernel<<<gQKV, 256>>>(out, gate, w_down, x1, BT, DM, DFF);
}

// round 2
// speedup vs baseline: 1.8064x; 1.8064x over previous
#include <cuda_runtime.h>
#include <cuda_bf16.h>
#include <math.h>

// ---------------------------------------------------------------------------
// Problem constants
// ---------------------------------------------------------------------------
#define BB     4
#define TT     2048
#define DM     256
#define DFF    1024
#define NH     4
#define DK     64
#define BT     (BB*TT)          // 8192 rows

// ---------------------------------------------------------------------------
// Scratch (device globals: allocation-free per harness rules)
// ---------------------------------------------------------------------------
__device__ float g_h   [BT*DM];
__device__ float g_q   [BT*DM];
__device__ float g_k   [BT*DM];
__device__ float g_v   [BT*DM];
__device__ float g_attn[BT*DM];
__device__ float g_x1  [BT*DM];
__device__ float g_hf  [BT*DM];
__device__ float g_gate[BT*DFF];
__device__ float g_up  [BT*DFF];

// ---------------------------------------------------------------------------
// tf32 helpers
// ---------------------------------------------------------------------------
__device__ __forceinline__ unsigned f2tf32(float x) {
    unsigned r;
    asm("cvt.rna.tf32.f32 %0, %1;" : "=r"(r) : "f"(x));
    return r;
}

__device__ __forceinline__ void mma_tf32(float* c, const unsigned* a, const unsigned* b) {
    asm volatile(
        "mma.sync.aligned.m16n8k8.row.col.f32.tf32.tf32.f32 "
        "{%0,%1,%2,%3}, {%4,%5,%6,%7}, {%8,%9}, {%0,%1,%2,%3};\n"
        : "+f"(c[0]), "+f"(c[1]), "+f"(c[2]), "+f"(c[3])
        : "r"(a[0]), "r"(a[1]), "r"(a[2]), "r"(a[3]), "r"(b[0]), "r"(b[1]));
}

// ---------------------------------------------------------------------------
// RMSNorm: one block per row of 256
// ---------------------------------------------------------------------------
__global__ void rmsnorm_kernel(float* __restrict__ out, const float* __restrict__ x,
                               const float* __restrict__ w) {
    int row = blockIdx.x;
    int tid = threadIdx.x;
    float vx = x[row*DM + tid];
    float ss = vx*vx;
    #pragma unroll
    for (int off = 16; off >= 1; off >>= 1) ss += __shfl_xor_sync(0xffffffffu, ss, off);
    __shared__ float ws[8];
    if ((tid & 31) == 0) ws[tid >> 5] = ss;
    __syncthreads();
    float tot = ws[0];
    #pragma unroll
    for (int i = 1; i < 8; ++i) tot += ws[i];
    float rinv = rsqrtf(tot * (1.0f/DM) + 1e-5f);
    out[row*DM + tid] = vx * rinv * w[tid];
}

// ---------------------------------------------------------------------------
// Tensor-core GEMM (tf32): C[M,N] = A[M,K] @ Bw[N,K]^T (+ res)
// Block tile 128x128, BK=32, 256 threads = 8 warps (4 row x 2 col),
// warp tile 32x64 = 2 x 8 m16n8k8 mma tiles.
// blockIdx.z selects among up to 3 (Bw, C) pairs (fused QKV / gate+up).
// ---------------------------------------------------------------------------
#define BM 128
#define BN 128
#define BK 32
#define TSTR 36   // smem row stride (words): conflict-free fragment loads

__global__ __launch_bounds__(256, 2)
void gemm_mma(const float* __restrict__ A,
              const float* __restrict__ B0, const float* __restrict__ B1,
              const float* __restrict__ B2,
              float* __restrict__ C0, float* __restrict__ C1, float* __restrict__ C2,
              const float* __restrict__ res,
              int M, int N, int K) {
    __shared__ unsigned As[BM * TSTR];
    __shared__ unsigned Bs[BN * TSTR];

    const float* Bw = (blockIdx.z == 0) ? B0 : (blockIdx.z == 1 ? B1 : B2);
    float*       C  = (blockIdx.z == 0) ? C0 : (blockIdx.z == 1 ? C1 : C2);

    const int tid  = threadIdx.x;
    const int lane = tid & 31;
    const int wid  = tid >> 5;
    const int wrow = wid >> 1;        // 0..3 -> 32-row slab
    const int wcol = wid & 1;         // 0..1 -> 64-col slab
    const int row0 = blockIdx.y * BM;
    const int col0 = blockIdx.x * BN;

    float acc[2][8][4];
    #pragma unroll
    for (int i = 0; i < 2; ++i)
        #pragma unroll
        for (int j = 0; j < 8; ++j)
            #pragma unroll
            for (int t = 0; t < 4; ++t) acc[i][j][t] = 0.f;

    const int gid  = tid;             // loader index
    for (int k0 = 0; k0 < K; k0 += BK) {
        // load A tile: 128x32 floats = 1024 float4, 4 per thread
        #pragma unroll
        for (int it = 0; it < 4; ++it) {
            int idx = it*256 + gid;
            int r = idx >> 3, c4 = (idx & 7) * 4;
            float4 vv = *(const float4*)(A + (size_t)(row0 + r)*K + k0 + c4);
            uint4 tv = { f2tf32(vv.x), f2tf32(vv.y), f2tf32(vv.z), f2tf32(vv.w) };
            *(uint4*)(As + r*TSTR + c4) = tv;
        }
        // load B tile: 128x32 (rows = output cols)
        #pragma unroll
        for (int it = 0; it < 4; ++it) {
            int idx = it*256 + gid;
            int r = idx >> 3, c4 = (idx & 7) * 4;
            float4 vv = *(const float4*)(Bw + (size_t)(col0 + r)*K + k0 + c4);
            uint4 tv = { f2tf32(vv.x), f2tf32(vv.y), f2tf32(vv.z), f2tf32(vv.w) };
            *(uint4*)(Bs + r*TSTR + c4) = tv;
        }
        __syncthreads();

        #pragma unroll
        for (int ks = 0; ks < 4; ++ks) {
            const int k = ks * 8;
            unsigned a[2][4], b[8][2];
            #pragma unroll
            for (int i = 0; i < 2; ++i) {
                int r = wrow*32 + i*16 + (lane >> 2);
                a[i][0] = As[ r      *TSTR + k + (lane & 3)    ];
                a[i][1] = As[(r + 8) *TSTR + k + (lane & 3)    ];
                a[i][2] = As[ r      *TSTR + k + (lane & 3) + 4];
                a[i][3] = As[(r + 8) *TSTR + k + (lane & 3) + 4];
            }
            #pragma unroll
            for (int j = 0; j < 8; ++j) {
                int n = wcol*64 + j*8 + (lane >> 2);
                b[j][0] = Bs[n*TSTR + k + (lane & 3)    ];
                b[j][1] = Bs[n*TSTR + k + (lane & 3) + 4];
            }
            #pragma unroll
            for (int i = 0; i < 2; ++i)
                #pragma unroll
                for (int j = 0; j < 8; ++j)
                    mma_tf32(acc[i][j], a[i], b[j]);
        }
        __syncthreads();
    }

    // epilogue: c0,c1 = row g, cols 2t,2t+1 ; c2,c3 = row g+8
    #pragma unroll
    for (int i = 0; i < 2; ++i) {
        int r = row0 + wrow*32 + i*16 + (lane >> 2);
        #pragma unroll
        for (int j = 0; j < 8; ++j) {
            int c = col0 + wcol*64 + j*8 + (lane & 3)*2;
            float2 v01 = { acc[i][j][0], acc[i][j][1] };
            float2 v23 = { acc[i][j][2], acc[i][j][3] };
            if (res) {
                float2 r01 = *(const float2*)(res + (size_t)r*N + c);
                float2 r23 = *(const float2*)(res + (size_t)(r+8)*N + c);
                v01.x += r01.x; v01.y += r01.y;
                v23.x += r23.x; v23.y += r23.y;
            }
            *(float2*)(C + (size_t)r*N + c)     = v01;
            *(float2*)(C + (size_t)(r+8)*N + c) = v23;
        }
    }
}

// ---------------------------------------------------------------------------
// Flash attention: block = (qtile 64 rows, one (b,h)); causal; online softmax
// 256 threads, 4x4 micro-tile per thread on 64x64 tiles (SIMT fp32)
// ---------------------------------------------------------------------------
__global__ __launch_bounds__(256, 3)
void attn_kernel(float* __restrict__ out, const float* __restrict__ q,
                 const float* __restrict__ k, const float* __restrict__ v) {
    extern __shared__ float sm[];
    float* Qs = sm;                 // 64*64
    float* Ks = Qs + 64*64;         // 64*65 (padded)
    float* Vs = Ks + 64*65;         // 64*64
    float* Ps = Vs + 64*64;         // 64*65 (padded)

    int tid = threadIdx.x;
    int tx = tid & 15, ty = tid >> 4;
    int qtile = blockIdx.x;
    int bh = blockIdx.y;
    int b = bh >> 2, h = bh & 3;
    int q0 = qtile * 64;
    size_t base = ((size_t)b * TT) * DM + (size_t)h * DK;

    #pragma unroll
    for (int l = 0; l < 16; ++l) {
        int e = l*256 + tid;
        int i = e >> 6, d = e & 63;
        Qs[i*64 + d] = q[base + (size_t)(q0+i)*DM + d];
    }

    float m_i[4], l_i[4], o[4][4];
    #pragma unroll
    for (int r = 0; r < 4; ++r) {
        m_i[r] = -1e30f; l_i[r] = 0.f;
        #pragma unroll
        for (int c = 0; c < 4; ++c) o[r][c] = 0.f;
    }
    const float scale = 0.125f;

    for (int jt = 0; jt <= qtile; ++jt) {
        int k0 = jt * 64;
        __syncthreads();
        #pragma unroll
        for (int l = 0; l < 16; ++l) {
            int e = l*256 + tid;
            int i = e >> 6, d = e & 63;
            Ks[i*65 + d] = k[base + (size_t)(k0+i)*DM + d];
            Vs[i*64 + d] = v[base + (size_t)(k0+i)*DM + d];
        }
        __syncthreads();

        float s[4][4];
        #pragma unroll
        for (int r = 0; r < 4; ++r)
            #pragma unroll
            for (int c = 0; c < 4; ++c) s[r][c] = 0.f;
        #pragma unroll 8
        for (int d = 0; d < 64; ++d) {
            float qa[4], kb[4];
            #pragma unroll
            for (int r = 0; r < 4; ++r) qa[r] = Qs[(ty*4+r)*64 + d];
            #pragma unroll
            for (int c = 0; c < 4; ++c) kb[c] = Ks[(tx*4+c)*65 + d];
            #pragma unroll
            for (int r = 0; r < 4; ++r)
                #pragma unroll
                for (int c = 0; c < 4; ++c) s[r][c] += qa[r]*kb[c];
        }
        #pragma unroll
        for (int r = 0; r < 4; ++r)
            #pragma unroll
            for (int c = 0; c < 4; ++c) {
                int qi = q0 + ty*4 + r, kj = k0 + tx*4 + c;
                s[r][c] = (kj <= qi) ? s[r][c]*scale : -1e30f;
            }
        float mnew[4], alpha[4];
        #pragma unroll
        for (int r = 0; r < 4; ++r) {
            float mx = fmaxf(fmaxf(s[r][0], s[r][1]), fmaxf(s[r][2], s[r][3]));
            #pragma unroll
            for (int off = 8; off >= 1; off >>= 1)
                mx = fmaxf(mx, __shfl_xor_sync(0xffffffffu, mx, off));
            mnew[r] = fmaxf(m_i[r], mx);
            alpha[r] = __expf(m_i[r] - mnew[r]);
            m_i[r] = mnew[r];
        }
        #pragma unroll
        for (int r = 0; r < 4; ++r) {
            float rs = 0.f;
            #pragma unroll
            for (int c = 0; c < 4; ++c) {
                float p = __expf(s[r][c] - mnew[r]);
                s[r][c] = p; rs += p;
            }
            #pragma unroll
            for (int off = 8; off >= 1; off >>= 1)
                rs += __shfl_xor_sync(0xffffffffu, rs, off);
            l_i[r] = l_i[r]*alpha[r] + rs;
        }
        #pragma unroll
        for (int r = 0; r < 4; ++r)
            #pragma unroll
            for (int c = 0; c < 4; ++c)
                Ps[(ty*4+r)*65 + tx*4+c] = s[r][c];
        __syncthreads();
        #pragma unroll
        for (int r = 0; r < 4; ++r)
            #pragma unroll
            for (int c = 0; c < 4; ++c) o[r][c] *= alpha[r];
        #pragma unroll 8
        for (int kk = 0; kk < 64; ++kk) {
            float pa[4], vb[4];
            #pragma unroll
            for (int r = 0; r < 4; ++r) pa[r] = Ps[(ty*4+r)*65 + kk];
            #pragma unroll
            for (int c = 0; c < 4; ++c) vb[c] = Vs[kk*64 + tx*4+c];
            #pragma unroll
            for (int r = 0; r < 4; ++r)
                #pragma unroll
                for (int c = 0; c < 4; ++c) o[r][c] += pa[r]*vb[c];
        }
    }

    #pragma unroll
    for (int r = 0; r < 4; ++r) {
        float inv = 1.f / l_i[r];
        int qi = q0 + ty*4 + r;
        #pragma unroll
        for (int c = 0; c < 4; ++c)
            out[base + (size_t)qi*DM + tx*4 + c] = o[r][c]*inv;
    }
}

// ---------------------------------------------------------------------------
// SiLU(gate) * up, in place into gate buffer (vectorized)
// ---------------------------------------------------------------------------
__global__ void silu_mul_kernel(float* __restrict__ g, const float* __restrict__ u, int n4) {
    int i = blockIdx.x*blockDim.x + threadIdx.x;
    int stride = gridDim.x*blockDim.x;
    float4* g4 = (float4*)g;
    const float4* u4 = (const float4*)u;
    for (; i < n4; i += stride) {
        float4 gv = g4[i];
        float4 uv = u4[i];
        gv.x = gv.x / (1.f + __expf(-gv.x)) * uv.x;
        gv.y = gv.y / (1.f + __expf(-gv.y)) * uv.y;
        gv.z = gv.z / (1.f + __expf(-gv.z)) * uv.z;
        gv.w = gv.w / (1.f + __expf(-gv.w)) * uv.w;
        g4[i] = gv;
    }
}

// ---------------------------------------------------------------------------
// Launch
// ---------------------------------------------------------------------------
extern "C" void kernel_launch(void* const* d_in, const int* in_sizes, int n_in,
                              void* d_out, int out_size) {
    const float* x        = (const float*)d_in[0];
    const float* rms_attn = (const float*)d_in[2];
    const float* wq       = (const float*)d_in[3];
    const float* wk       = (const float*)d_in[4];
    const float* wv       = (const float*)d_in[5];
    const float* wo       = (const float*)d_in[6];
    const float* rms_ffn  = (const float*)d_in[7];
    const float* w_gate   = (const float*)d_in[8];
    const float* w_up     = (const float*)d_in[9];
    const float* w_down   = (const float*)d_in[10];
    float* out = (float*)d_out;

    float *h, *q, *k, *v, *attn, *x1, *hf, *gate, *up;
    cudaGetSymbolAddress((void**)&h,    g_h);
    cudaGetSymbolAddress((void**)&q,    g_q);
    cudaGetSymbolAddress((void**)&k,    g_k);
    cudaGetSymbolAddress((void**)&v,    g_v);
    cudaGetSymbolAddress((void**)&attn, g_attn);
    cudaGetSymbolAddress((void**)&x1,   g_x1);
    cudaGetSymbolAddress((void**)&hf,   g_hf);
    cudaGetSymbolAddress((void**)&gate, g_gate);
    cudaGetSymbolAddress((void**)&up,   g_up);

    static const size_t attn_smem = (size_t)(64*64 + 64*65 + 64*64 + 64*65) * sizeof(float);
    cudaFuncSetAttribute(attn_kernel, cudaFuncAttributeMaxDynamicSharedMemorySize, (int)attn_smem);

    // 1. h = rmsnorm(x)
    rmsnorm_kernel<<<BT, 256>>>(h, x, rms_attn);

    // 2. fused q,k,v projections (tensor cores)
    dim3 gQKV(DM/BN, BT/BM, 3);
    gemm_mma<<<gQKV, 256>>>(h, wq, wk, wv, q, k, v, nullptr, BT, DM, DM);

    // 3. attention
    dim3 gAttn(TT/64, BB*NH);
    attn_kernel<<<gAttn, 256, attn_smem>>>(attn, q, k, v);

    // 4. x1 = x + attn @ wo^T
    dim3 gO(DM/BN, BT/BM, 1);
    gemm_mma<<<gO, 256>>>(attn, wo, wo, wo, x1, x1, x1, x, BT, DM, DM);

    // 5. hf = rmsnorm(x1)
    rmsnorm_kernel<<<BT, 256>>>(hf, x1, rms_ffn);

    // 6. fused gate/up
    dim3 gFF(DFF/BN, BT/BM, 2);
    gemm_mma<<<gFF, 256>>>(hf, w_gate, w_up, w_up, gate, up, up, nullptr, BT, DFF, DM);

    // 7. gate = silu(gate)*up
    silu_mul_kernel<<<2048, 256>>>(gate, up, BT*DFF/4);

    // 8. out = x1 + gate @ w_down^T
    dim3 gD(DM/BN, BT/BM, 1);
    gemm_mma<<<gD, 256>>>(gate, w_down, w_down, w_down, out, out, out, x1, BT, DM, DFF);
}

// round 5
// speedup vs baseline: 3.3979x; 1.8810x over previous
#include <cuda_runtime.h>
#include <cuda_bf16.h>
#include <math.h>

// ---------------------------------------------------------------------------
// Problem constants
// ---------------------------------------------------------------------------
#define BB     4
#define TT     2048
#define DM     256
#define DFF    1024
#define NH     4
#define DK     64
#define BT     (BB*TT)          // 8192 rows

// ---------------------------------------------------------------------------
// Scratch
// ---------------------------------------------------------------------------
__device__ float g_h   [BT*DM];
__device__ float g_q   [BT*DM];
__device__ float g_k   [BT*DM];
__device__ float g_v   [BT*DM];
__device__ float g_attn[BT*DM];
__device__ float g_x1  [BT*DM];
__device__ float g_hf  [BT*DM];
__device__ float g_gate[BT*DFF];
__device__ float g_up  [BT*DFF];

// ---------------------------------------------------------------------------
// helpers
// ---------------------------------------------------------------------------
__device__ __forceinline__ void mma_tf32(float* c, const unsigned* a, const unsigned* b) {
    asm volatile(
        "mma.sync.aligned.m16n8k8.row.col.f32.tf32.tf32.f32 "
        "{%0,%1,%2,%3}, {%4,%5,%6,%7}, {%8,%9}, {%0,%1,%2,%3};\n"
        : "+f"(c[0]), "+f"(c[1]), "+f"(c[2]), "+f"(c[3])
        : "r"(a[0]), "r"(a[1]), "r"(a[2]), "r"(a[3]), "r"(b[0]), "r"(b[1]));
}

__device__ __forceinline__ void cpa16(float* s, const float* g) {
    unsigned sa = (unsigned)__cvta_generic_to_shared(s);
    asm volatile("cp.async.cg.shared.global [%0], [%1], 16;" :: "r"(sa), "l"(g));
}
__device__ __forceinline__ void cp_commit() { asm volatile("cp.async.commit_group;"); }
template<int N> __device__ __forceinline__ void cp_wait() {
    asm volatile("cp.async.wait_group %0;" :: "n"(N));
}

// ---------------------------------------------------------------------------
// RMSNorm
// ---------------------------------------------------------------------------
__global__ void rmsnorm_kernel(float* __restrict__ out, const float* __restrict__ x,
                               const float* __restrict__ w) {
    int row = blockIdx.x;
    int tid = threadIdx.x;
    float vx = x[row*DM + tid];
    float ss = vx*vx;
    #pragma unroll
    for (int off = 16; off >= 1; off >>= 1) ss += __shfl_xor_sync(0xffffffffu, ss, off);
    __shared__ float ws[8];
    if ((tid & 31) == 0) ws[tid >> 5] = ss;
    __syncthreads();
    float tot = ws[0];
    #pragma unroll
    for (int i = 1; i < 8; ++i) tot += ws[i];
    float rinv = rsqrtf(tot * (1.0f/DM) + 1e-5f);
    out[row*DM + tid] = vx * rinv * w[tid];
}

// ---------------------------------------------------------------------------
// Tensor-core GEMM (tf32 via raw fp32 bits): C[M,N] = A[M,K] @ Bw[N,K]^T (+res)
// 128 x BN_ tile, BK=32, double-buffered cp.async, 8 warps (4x2)
// ---------------------------------------------------------------------------
#define TSTR 36

template<int BN_>
__global__ __launch_bounds__(256, 2)
void gemm_mma(const float* __restrict__ A,
              const float* __restrict__ B0, const float* __restrict__ B1,
              const float* __restrict__ B2,
              float* __restrict__ C0, float* __restrict__ C1, float* __restrict__ C2,
              const float* __restrict__ res,
              int M, int N, int K) {
    constexpr int WN  = BN_/16;       // n-tiles per warp
    constexpr int ASZ = 128*TSTR;
    constexpr int BSZ = BN_*TSTR;
    extern __shared__ float smf[];
    float* As = smf;                  // 2 stages
    float* Bs = smf + 2*ASZ;

    const float* Bw = (blockIdx.z == 0) ? B0 : (blockIdx.z == 1 ? B1 : B2);
    float*       C  = (blockIdx.z == 0) ? C0 : (blockIdx.z == 1 ? C1 : C2);

    const int tid = threadIdx.x, lane = tid & 31, wid = tid >> 5;
    const int wrow = wid >> 1, wcol = wid & 1;
    const int row0 = blockIdx.y * 128;
    const int col0 = blockIdx.x * BN_;

    float acc[2][WN][4];
    #pragma unroll
    for (int i = 0; i < 2; ++i)
        #pragma unroll
        for (int j = 0; j < WN; ++j)
            #pragma unroll
            for (int t = 0; t < 4; ++t) acc[i][j][t] = 0.f;

    auto load_stage = [&](int k0, int st) {
        float* as = As + st*ASZ;
        float* bs = Bs + st*BSZ;
        #pragma unroll
        for (int it = 0; it < 4; ++it) {
            int idx = it*256 + tid, r = idx >> 3, c4 = (idx & 7)*4;
            cpa16(as + r*TSTR + c4, A + (size_t)(row0 + r)*K + k0 + c4);
        }
        #pragma unroll
        for (int it = 0; it < BN_/32; ++it) {
            int idx = it*256 + tid, r = idx >> 3, c4 = (idx & 7)*4;
            cpa16(bs + r*TSTR + c4, Bw + (size_t)(col0 + r)*K + k0 + c4);
        }
        cp_commit();
    };

    const int nt = K / 32;
    load_stage(0, 0);
    for (int t = 0; t < nt; ++t) {
        if (t + 1 < nt) { load_stage((t+1)*32, (t+1) & 1); cp_wait<1>(); }
        else            { cp_wait<0>(); }
        __syncthreads();
        const float* as = As + (t & 1)*ASZ;
        const float* bs = Bs + (t & 1)*BSZ;
        #pragma unroll
        for (int ks = 0; ks < 4; ++ks) {
            const int k = ks*8;
            unsigned a[2][4], b[WN][2];
            #pragma unroll
            for (int i = 0; i < 2; ++i) {
                int r = wrow*32 + i*16 + (lane >> 2);
                a[i][0] = __float_as_uint(as[ r     *TSTR + k + (lane & 3)    ]);
                a[i][1] = __float_as_uint(as[(r + 8)*TSTR + k + (lane & 3)    ]);
                a[i][2] = __float_as_uint(as[ r     *TSTR + k + (lane & 3) + 4]);
                a[i][3] = __float_as_uint(as[(r + 8)*TSTR + k + (lane & 3) + 4]);
            }
            #pragma unroll
            for (int j = 0; j < WN; ++j) {
                int n = wcol*(BN_/2) + j*8 + (lane >> 2);
                b[j][0] = __float_as_uint(bs[n*TSTR + k + (lane & 3)    ]);
                b[j][1] = __float_as_uint(bs[n*TSTR + k + (lane & 3) + 4]);
            }
            #pragma unroll
            for (int i = 0; i < 2; ++i)
                #pragma unroll
                for (int j = 0; j < WN; ++j)
                    mma_tf32(acc[i][j], a[i], b[j]);
        }
        __syncthreads();
    }

    #pragma unroll
    for (int i = 0; i < 2; ++i) {
        int r = row0 + wrow*32 + i*16 + (lane >> 2);
        #pragma unroll
        for (int j = 0; j < WN; ++j) {
            int c = col0 + wcol*(BN_/2) + j*8 + (lane & 3)*2;
            float2 v01 = { acc[i][j][0], acc[i][j][1] };
            float2 v23 = { acc[i][j][2], acc[i][j][3] };
            if (res) {
                float2 r01 = *(const float2*)(res + (size_t)r*N + c);
                float2 r23 = *(const float2*)(res + (size_t)(r+8)*N + c);
                v01.x += r01.x; v01.y += r01.y;
                v23.x += r23.x; v23.y += r23.y;
            }
            *(float2*)(C + (size_t)r*N + c)     = v01;
            *(float2*)(C + (size_t)(r+8)*N + c) = v23;
        }
    }
}

// ---------------------------------------------------------------------------
// Tensor-core flash attention (tf32 mma, fp32 softmax)
// block: 128 q-rows x one (b,h); 8 warps x 16 rows; K/V tiles of 64
// ---------------------------------------------------------------------------
#define QSTR 68
#define KSTR 68
#define VSTR 72
#define PSTR 68

__global__ __launch_bounds__(256, 2)
void attn_mma(float* __restrict__ out, const float* __restrict__ q,
              const float* __restrict__ k, const float* __restrict__ v) {
    extern __shared__ float smf[];
    float* Qs = smf;                   // 128 x QSTR
    float* Ks = Qs + 128*QSTR;         // 64 x KSTR
    float* Vs = Ks + 64*KSTR;          // 64 x VSTR
    float* Ps = Vs + 64*VSTR;          // 128 x PSTR (warp-private 16-row slabs)

    const int tid = threadIdx.x, lane = tid & 31, wid = tid >> 5;
    const int bh = blockIdx.x;
    const int qx = blockIdx.y;
    const int b = bh >> 2, h = bh & 3;
    const int q0 = qx * 128;
    const size_t base = (size_t)b*TT*DM + (size_t)h*DK;

    // Q tile -> smem (raw bits)
    #pragma unroll
    for (int it = 0; it < 8; ++it) {
        int idx = it*256 + tid, r = idx >> 4, c4 = (idx & 15)*4;
        cpa16(Qs + r*QSTR + c4, q + base + (size_t)(q0 + r)*DM + c4);
    }
    cp_commit();

    float o[8][4];
    #pragma unroll
    for (int j = 0; j < 8; ++j)
        #pragma unroll
        for (int t = 0; t < 4; ++t) o[j][t] = 0.f;
    float m0 = -1e30f, m1 = -1e30f, l0 = 0.f, l1 = 0.f;
    const int r0l = wid*16 + (lane >> 2);     // local q-row (first of pair)

    const int ntile = 2*qx + 2;
    for (int jt = 0; jt < ntile; ++jt) {
        const int k0 = jt*64;
        __syncthreads();   // prior-iteration Ks/Vs reads complete
        #pragma unroll
        for (int it = 0; it < 4; ++it) {
            int idx = it*256 + tid, r = idx >> 4, c4 = (idx & 15)*4;
            cpa16(Ks + r*KSTR + c4, k + base + (size_t)(k0 + r)*DM + c4);
            cpa16(Vs + r*VSTR + c4, v + base + (size_t)(k0 + r)*DM + c4);
        }
        cp_commit();
        cp_wait<0>();
        __syncthreads();

        // ---- S = Q @ K^T (16x64 per warp) ----
        float s[8][4];
        #pragma unroll
        for (int j = 0; j < 8; ++j)
            #pragma unroll
            for (int t = 0; t < 4; ++t) s[j][t] = 0.f;
        #pragma unroll
        for (int ks = 0; ks < 8; ++ks) {
            const int kk = ks*8;
            unsigned aq[4];
            aq[0] = __float_as_uint(Qs[ r0l     *QSTR + kk + (lane & 3)    ]);
            aq[1] = __float_as_uint(Qs[(r0l + 8)*QSTR + kk + (lane & 3)    ]);
            aq[2] = __float_as_uint(Qs[ r0l     *QSTR + kk + (lane & 3) + 4]);
            aq[3] = __float_as_uint(Qs[(r0l + 8)*QSTR + kk + (lane & 3) + 4]);
            #pragma unroll
            for (int j = 0; j < 8; ++j) {
                unsigned bv[2];
                int n = j*8 + (lane >> 2);
                bv[0] = __float_as_uint(Ks[n*KSTR + kk + (lane & 3)    ]);
                bv[1] = __float_as_uint(Ks[n*KSTR + kk + (lane & 3) + 4]);
                mma_tf32(s[j], aq, bv);
            }
        }

        // ---- scale + causal mask ----
        const float sc = 0.125f;
        if (jt >= 2*qx) {
            const int row_a = q0 + r0l, row_b = row_a + 8;
            #pragma unroll
            for (int j = 0; j < 8; ++j) {
                int col = k0 + j*8 + 2*(lane & 3);
                s[j][0] = (col     <= row_a) ? s[j][0]*sc : -1e30f;
                s[j][1] = (col + 1 <= row_a) ? s[j][1]*sc : -1e30f;
                s[j][2] = (col     <= row_b) ? s[j][2]*sc : -1e30f;
                s[j][3] = (col + 1 <= row_b) ? s[j][3]*sc : -1e30f;
            }
        } else {
            #pragma unroll
            for (int j = 0; j < 8; ++j)
                #pragma unroll
                for (int t = 0; t < 4; ++t) s[j][t] *= sc;
        }

        // ---- online softmax (rows r0l and r0l+8) ----
        float mx0 = -1e30f, mx1 = -1e30f;
        #pragma unroll
        for (int j = 0; j < 8; ++j) {
            mx0 = fmaxf(mx0, fmaxf(s[j][0], s[j][1]));
            mx1 = fmaxf(mx1, fmaxf(s[j][2], s[j][3]));
        }
        #pragma unroll
        for (int off = 1; off <= 2; off <<= 1) {
            mx0 = fmaxf(mx0, __shfl_xor_sync(0xffffffffu, mx0, off));
            mx1 = fmaxf(mx1, __shfl_xor_sync(0xffffffffu, mx1, off));
        }
        float mn0 = fmaxf(m0, mx0), mn1 = fmaxf(m1, mx1);
        float al0 = __expf(m0 - mn0), al1 = __expf(m1 - mn1);
        m0 = mn0; m1 = mn1;
        float rs0 = 0.f, rs1 = 0.f;
        #pragma unroll
        for (int j = 0; j < 8; ++j) {
            s[j][0] = __expf(s[j][0] - mn0); rs0 += s[j][0];
            s[j][1] = __expf(s[j][1] - mn0); rs0 += s[j][1];
            s[j][2] = __expf(s[j][2] - mn1); rs1 += s[j][2];
            s[j][3] = __expf(s[j][3] - mn1); rs1 += s[j][3];
        }
        #pragma unroll
        for (int off = 1; off <= 2; off <<= 1) {
            rs0 += __shfl_xor_sync(0xffffffffu, rs0, off);
            rs1 += __shfl_xor_sync(0xffffffffu, rs1, off);
        }
        l0 = l0*al0 + rs0;
        l1 = l1*al1 + rs1;

        // ---- stage P (warp-private rows) ----
        #pragma unroll
        for (int j = 0; j < 8; ++j) {
            int cc = j*8 + 2*(lane & 3);
            *(float2*)(Ps + (size_t)r0l*PSTR + cc)       = make_float2(s[j][0], s[j][1]);
            *(float2*)(Ps + (size_t)(r0l + 8)*PSTR + cc) = make_float2(s[j][2], s[j][3]);
        }
        __syncwarp();

        // ---- O = O*alpha + P @ V ----
        #pragma unroll
        for (int j = 0; j < 8; ++j) {
            o[j][0] *= al0; o[j][1] *= al0;
            o[j][2] *= al1; o[j][3] *= al1;
        }
        #pragma unroll
        for (int ks = 0; ks < 8; ++ks) {
            const int kk = ks*8;
            unsigned ap[4];
            ap[0] = __float_as_uint(Ps[ r0l     *PSTR + kk + (lane & 3)    ]);
            ap[1] = __float_as_uint(Ps[(r0l + 8)*PSTR + kk + (lane & 3)    ]);
            ap[2] = __float_as_uint(Ps[ r0l     *PSTR + kk + (lane & 3) + 4]);
            ap[3] = __float_as_uint(Ps[(r0l + 8)*PSTR + kk + (lane & 3) + 4]);
            #pragma unroll
            for (int j = 0; j < 8; ++j) {
                unsigned bv[2];
                bv[0] = __float_as_uint(Vs[(kk + (lane & 3)    )*VSTR + j*8 + (lane >> 2)]);
                bv[1] = __float_as_uint(Vs[(kk + (lane & 3) + 4)*VSTR + j*8 + (lane >> 2)]);
                mma_tf32(o[j], ap, bv);
            }
        }
    }

    // ---- epilogue ----
    const float inv0 = 1.f / l0, inv1 = 1.f / l1;
    const int grow = q0 + r0l;
    #pragma unroll
    for (int j = 0; j < 8; ++j) {
        int cc = j*8 + 2*(lane & 3);
        *(float2*)(out + base + (size_t)grow*DM + cc) =
            make_float2(o[j][0]*inv0, o[j][1]*inv0);
        *(float2*)(out + base + (size_t)(grow + 8)*DM + cc) =
            make_float2(o[j][2]*inv1, o[j][3]*inv1);
    }
}

// ---------------------------------------------------------------------------
// SiLU(gate) * up
// ---------------------------------------------------------------------------
__global__ void silu_mul_kernel(float* __restrict__ g, const float* __restrict__ u, int n4) {
    int i = blockIdx.x*blockDim.x + threadIdx.x;
    int stride = gridDim.x*blockDim.x;
    float4* g4 = (float4*)g;
    const float4* u4 = (const float4*)u;
    for (; i < n4; i += stride) {
        float4 gv = g4[i];
        float4 uv = u4[i];
        gv.x = gv.x / (1.f + __expf(-gv.x)) * uv.x;
        gv.y = gv.y / (1.f + __expf(-gv.y)) * uv.y;
        gv.z = gv.z / (1.f + __expf(-gv.z)) * uv.z;
        gv.w = gv.w / (1.f + __expf(-gv.w)) * uv.w;
        g4[i] = gv;
    }
}

// ---------------------------------------------------------------------------
// Launch
// ---------------------------------------------------------------------------
extern "C" void kernel_launch(void* const* d_in, const int* in_sizes, int n_in,
                              void* d_out, int out_size) {
    const float* x        = (const float*)d_in[0];
    const float* rms_attn = (const float*)d_in[2];
    const float* wq       = (const float*)d_in[3];
    const float* wk       = (const float*)d_in[4];
    const float* wv       = (const float*)d_in[5];
    const float* wo       = (const float*)d_in[6];
    const float* rms_ffn  = (const float*)d_in[7];
    const float* w_gate   = (const float*)d_in[8];
    const float* w_up     = (const float*)d_in[9];
    const float* w_down   = (const float*)d_in[10];
    float* out = (float*)d_out;

    float *h, *q, *k, *v, *attn, *x1, *hf, *gate, *up;
    cudaGetSymbolAddress((void**)&h,    g_h);
    cudaGetSymbolAddress((void**)&q,    g_q);
    cudaGetSymbolAddress((void**)&k,    g_k);
    cudaGetSymbolAddress((void**)&v,    g_v);
    cudaGetSymbolAddress((void**)&attn, g_attn);
    cudaGetSymbolAddress((void**)&x1,   g_x1);
    cudaGetSymbolAddress((void**)&hf,   g_hf);
    cudaGetSymbolAddress((void**)&gate, g_gate);
    cudaGetSymbolAddress((void**)&up,   g_up);

    const int GS128 = 2*(128 + 128)*TSTR*4;                               // 73728
    const int GS64  = 2*(128 +  64)*TSTR*4;                               // 55296
    const int ASM   = (128*QSTR + 64*KSTR + 64*VSTR + 128*PSTR)*4;        // 105472
    cudaFuncSetAttribute(gemm_mma<128>, cudaFuncAttributeMaxDynamicSharedMemorySize, GS128);
    cudaFuncSetAttribute(gemm_mma<64>,  cudaFuncAttributeMaxDynamicSharedMemorySize, GS64);
    cudaFuncSetAttribute(attn_mma,      cudaFuncAttributeMaxDynamicSharedMemorySize, ASM);

    // 1. h = rmsnorm(x)
    rmsnorm_kernel<<<BT, 256>>>(h, x, rms_attn);

    // 2. fused q,k,v projections
    gemm_mma<128><<<dim3(DM/128, BT/128, 3), 256, GS128>>>(
        h, wq, wk, wv, q, k, v, nullptr, BT, DM, DM);

    // 3. attention (tensor cores)
    attn_mma<<<dim3(BB*NH, TT/128), 256, ASM>>>(attn, q, k, v);

    // 4. x1 = x + attn @ wo^T
    gemm_mma<64><<<dim3(DM/64, BT/128, 1), 256, GS64>>>(
        attn, wo, wo, wo, x1, x1, x1, x, BT, DM, DM);

    // 5. hf = rmsnorm(x1)
    rmsnorm_kernel<<<BT, 256>>>(hf, x1, rms_ffn);

    // 6. fused gate/up
    gemm_mma<128><<<dim3(DFF/128, BT/128, 2), 256, GS128>>>(
        hf, w_gate, w_up, w_up, gate, up, up, nullptr, BT, DFF, DM);

    // 7. gate = silu(gate)*up
    silu_mul_kernel<<<2048, 256>>>(gate, up, BT*DFF/4);

    // 8. out = x1 + gate @ w_down^T
    gemm_mma<64><<<dim3(DM/64, BT/128, 1), 256, GS64>>>(
        gate, w_down, w_down, w_down, out, out, out, x1, BT, DM, DFF);
}

// round 7
// speedup vs baseline: 3.5149x; 1.0344x over previous
#include <cuda_runtime.h>
#include <cuda_bf16.h>
#include <math.h>

// ---------------------------------------------------------------------------
// Problem constants
// ---------------------------------------------------------------------------
#define BB     4
#define TT     2048
#define DM     256
#define DFF    1024
#define NH     4
#define DK     64
#define BT     (BB*TT)          // 8192 rows

// ---------------------------------------------------------------------------
// Scratch
// ---------------------------------------------------------------------------
__device__ float g_h   [BT*DM];
__device__ float g_q   [BT*DM];
__device__ float g_k   [BT*DM];
__device__ float g_v   [BT*DM];
__device__ float g_attn[BT*DM];
__device__ float g_x1  [BT*DM];
__device__ float g_hf  [BT*DM];
__device__ float g_gate[BT*DFF];
__device__ float g_up  [BT*DFF];

// ---------------------------------------------------------------------------
// helpers
// ---------------------------------------------------------------------------
__device__ __forceinline__ void mma_tf32(float* c, const unsigned* a, const unsigned* b) {
    asm volatile(
        "mma.sync.aligned.m16n8k8.row.col.f32.tf32.tf32.f32 "
        "{%0,%1,%2,%3}, {%4,%5,%6,%7}, {%8,%9}, {%0,%1,%2,%3};\n"
        : "+f"(c[0]), "+f"(c[1]), "+f"(c[2]), "+f"(c[3])
        : "r"(a[0]), "r"(a[1]), "r"(a[2]), "r"(a[3]), "r"(b[0]), "r"(b[1]));
}

__device__ __forceinline__ void cpa16(float* s, const float* g) {
    unsigned sa = (unsigned)__cvta_generic_to_shared(s);
    asm volatile("cp.async.cg.shared.global [%0], [%1], 16;" :: "r"(sa), "l"(g));
}
__device__ __forceinline__ void cp_commit() { asm volatile("cp.async.commit_group;"); }
template<int N> __device__ __forceinline__ void cp_wait() {
    asm volatile("cp.async.wait_group %0;" :: "n"(N));
}

// ---------------------------------------------------------------------------
// RMSNorm
// ---------------------------------------------------------------------------
__global__ void rmsnorm_kernel(float* __restrict__ out, const float* __restrict__ x,
                               const float* __restrict__ w) {
    int row = blockIdx.x;
    int tid = threadIdx.x;
    float vx = x[row*DM + tid];
    float ss = vx*vx;
    #pragma unroll
    for (int off = 16; off >= 1; off >>= 1) ss += __shfl_xor_sync(0xffffffffu, ss, off);
    __shared__ float ws[8];
    if ((tid & 31) == 0) ws[tid >> 5] = ss;
    __syncthreads();
    float tot = ws[0];
    #pragma unroll
    for (int i = 1; i < 8; ++i) tot += ws[i];
    float rinv = rsqrtf(tot * (1.0f/DM) + 1e-5f);
    out[row*DM + tid] = vx * rinv * w[tid];
}

// ---------------------------------------------------------------------------
// Tensor-core GEMM (tf32): C[M,N] = A[M,K] @ Bw[N,K]^T (+res)
// 128 x BN_ tile, BK=32, 3-stage cp.async pipeline, 8 warps (4x2)
// ---------------------------------------------------------------------------
#define TSTR 36

template<int BN_>
__global__ __launch_bounds__(256, 2)
void gemm_mma(const float* __restrict__ A,
              const float* __restrict__ B0, const float* __restrict__ B1,
              const float* __restrict__ B2,
              float* __restrict__ C0, float* __restrict__ C1, float* __restrict__ C2,
              const float* __restrict__ res,
              int M, int N, int K) {
    constexpr int WN  = BN_/16;
    constexpr int ASZ = 128*TSTR;
    constexpr int BSZ = BN_*TSTR;
    extern __shared__ float smf[];
    float* As = smf;                  // 3 stages
    float* Bs = smf + 3*ASZ;

    const float* Bw = (blockIdx.z == 0) ? B0 : (blockIdx.z == 1 ? B1 : B2);
    float*       C  = (blockIdx.z == 0) ? C0 : (blockIdx.z == 1 ? C1 : C2);

    const int tid = threadIdx.x, lane = tid & 31, wid = tid >> 5;
    const int wrow = wid >> 1, wcol = wid & 1;
    const int row0 = blockIdx.y * 128;
    const int col0 = blockIdx.x * BN_;

    float acc[2][WN][4];
    #pragma unroll
    for (int i = 0; i < 2; ++i)
        #pragma unroll
        for (int j = 0; j < WN; ++j)
            #pragma unroll
            for (int t = 0; t < 4; ++t) acc[i][j][t] = 0.f;

    auto load_stage = [&](int k0, int st) {
        float* as = As + st*ASZ;
        float* bs = Bs + st*BSZ;
        #pragma unroll
        for (int it = 0; it < 4; ++it) {
            int idx = it*256 + tid, r = idx >> 3, c4 = (idx & 7)*4;
            cpa16(as + r*TSTR + c4, A + (size_t)(row0 + r)*K + k0 + c4);
        }
        #pragma unroll
        for (int it = 0; it < BN_/32; ++it) {
            int idx = it*256 + tid, r = idx >> 3, c4 = (idx & 7)*4;
            cpa16(bs + r*TSTR + c4, Bw + (size_t)(col0 + r)*K + k0 + c4);
        }
        cp_commit();
    };

    const int nt = K / 32;            // >= 8 for all our shapes
    load_stage(0, 0);
    load_stage(32, 1);
    for (int t = 0; t < nt; ++t) {
        if (t + 2 < nt)      { load_stage((t+2)*32, (t+2) % 3); cp_wait<2>(); }
        else if (t + 1 < nt) { cp_wait<1>(); }
        else                 { cp_wait<0>(); }
        __syncthreads();
        const float* as = As + (t % 3)*ASZ;
        const float* bs = Bs + (t % 3)*BSZ;
        #pragma unroll
        for (int ks = 0; ks < 4; ++ks) {
            const int k = ks*8;
            unsigned a[2][4], b[WN][2];
            #pragma unroll
            for (int i = 0; i < 2; ++i) {
                int r = wrow*32 + i*16 + (lane >> 2);
                a[i][0] = __float_as_uint(as[ r     *TSTR + k + (lane & 3)    ]);
                a[i][1] = __float_as_uint(as[(r + 8)*TSTR + k + (lane & 3)    ]);
                a[i][2] = __float_as_uint(as[ r     *TSTR + k + (lane & 3) + 4]);
                a[i][3] = __float_as_uint(as[(r + 8)*TSTR + k + (lane & 3) + 4]);
            }
            #pragma unroll
            for (int j = 0; j < WN; ++j) {
                int n = wcol*(BN_/2) + j*8 + (lane >> 2);
                b[j][0] = __float_as_uint(bs[n*TSTR + k + (lane & 3)    ]);
                b[j][1] = __float_as_uint(bs[n*TSTR + k + (lane & 3) + 4]);
            }
            #pragma unroll
            for (int i = 0; i < 2; ++i)
                #pragma unroll
                for (int j = 0; j < WN; ++j)
                    mma_tf32(acc[i][j], a[i], b[j]);
        }
        __syncthreads();
    }

    #pragma unroll
    for (int i = 0; i < 2; ++i) {
        int r = row0 + wrow*32 + i*16 + (lane >> 2);
        #pragma unroll
        for (int j = 0; j < WN; ++j) {
            int c = col0 + wcol*(BN_/2) + j*8 + (lane & 3)*2;
            float2 v01 = { acc[i][j][0], acc[i][j][1] };
            float2 v23 = { acc[i][j][2], acc[i][j][3] };
            if (res) {
                float2 r01 = *(const float2*)(res + (size_t)r*N + c);
                float2 r23 = *(const float2*)(res + (size_t)(r+8)*N + c);
                v01.x += r01.x; v01.y += r01.y;
                v23.x += r23.x; v23.y += r23.y;
            }
            *(float2*)(C + (size_t)r*N + c)     = v01;
            *(float2*)(C + (size_t)(r+8)*N + c) = v23;
        }
    }
}

// ---------------------------------------------------------------------------
// Tensor-core flash attention, double-buffered K/V, shuffle P-conversion
// block: 128 q-rows x one (b,h); 8 warps x 16 rows; K/V tiles of 64
// ---------------------------------------------------------------------------
#define QSTR 68
#define KSTR 68
#define VSTR 72

__global__ __launch_bounds__(256, 2)
void attn_mma(float* __restrict__ out, const float* __restrict__ q,
              const float* __restrict__ k, const float* __restrict__ v) {
    extern __shared__ float smf[];
    float* Qs = smf;                    // 128 x QSTR
    float* Ks = Qs + 128*QSTR;          // 2 stages of 64 x KSTR
    float* Vs = Ks + 2*64*KSTR;         // 2 stages of 64 x VSTR

    const int tid = threadIdx.x, lane = tid & 31, wid = tid >> 5;
    const int bh = blockIdx.x;
    const int qx = blockIdx.y;
    const int b = bh >> 2, h = bh & 3;
    const int q0 = qx * 128;
    const size_t base = (size_t)b*TT*DM + (size_t)h*DK;

    auto load_kv = [&](int jt, int st) {
        const int k0 = jt*64;
        float* ks_ = Ks + st*64*KSTR;
        float* vs_ = Vs + st*64*VSTR;
        #pragma unroll
        for (int it = 0; it < 4; ++it) {
            int idx = it*256 + tid, r = idx >> 4, c4 = (idx & 15)*4;
            cpa16(ks_ + r*KSTR + c4, k + base + (size_t)(k0 + r)*DM + c4);
            cpa16(vs_ + r*VSTR + c4, v + base + (size_t)(k0 + r)*DM + c4);
        }
        cp_commit();
    };

    // Q tile (group 0)
    #pragma unroll
    for (int it = 0; it < 8; ++it) {
        int idx = it*256 + tid, r = idx >> 4, c4 = (idx & 15)*4;
        cpa16(Qs + r*QSTR + c4, q + base + (size_t)(q0 + r)*DM + c4);
    }
    cp_commit();
    load_kv(0, 0);                      // group 1

    float o[8][4];
    #pragma unroll
    for (int j = 0; j < 8; ++j)
        #pragma unroll
        for (int t = 0; t < 4; ++t) o[j][t] = 0.f;
    float m0 = -1e30f, m1 = -1e30f, l0 = 0.f, l1 = 0.f;
    const int r0l = wid*16 + (lane >> 2);
    const int src0 = (lane & ~3) | ((lane & 3) >> 1);
    const int src1 = src0 + 2;
    const bool oddl = lane & 1;
    const float sc = 0.125f;

    const int ntile = 2*qx + 2;
    for (int jt = 0; jt < ntile; ++jt) {
        if (jt + 1 < ntile) { load_kv(jt+1, (jt+1) & 1); cp_wait<1>(); }
        else                { cp_wait<0>(); }
        __syncthreads();                // stage jt&1 visible to all
        const float* ks_ = Ks + (jt & 1)*64*KSTR;
        const float* vs_ = Vs + (jt & 1)*64*VSTR;
        const int k0 = jt*64;

        // ---- S = Q @ K^T (16x64 per warp), raw (unscaled) ----
        float s[8][4];
        #pragma unroll
        for (int j = 0; j < 8; ++j)
            #pragma unroll
            for (int t = 0; t < 4; ++t) s[j][t] = 0.f;
        #pragma unroll
        for (int ks = 0; ks < 8; ++ks) {
            const int kk = ks*8;
            unsigned aq[4];
            aq[0] = __float_as_uint(Qs[ r0l     *QSTR + kk + (lane & 3)    ]);
            aq[1] = __float_as_uint(Qs[(r0l + 8)*QSTR + kk + (lane & 3)    ]);
            aq[2] = __float_as_uint(Qs[ r0l     *QSTR + kk + (lane & 3) + 4]);
            aq[3] = __float_as_uint(Qs[(r0l + 8)*QSTR + kk + (lane & 3) + 4]);
            #pragma unroll
            for (int j = 0; j < 8; ++j) {
                unsigned bv[2];
                int n = j*8 + (lane >> 2);
                bv[0] = __float_as_uint(ks_[n*KSTR + kk + (lane & 3)    ]);
                bv[1] = __float_as_uint(ks_[n*KSTR + kk + (lane & 3) + 4]);
                mma_tf32(s[j], aq, bv);
            }
        }

        // ---- causal mask (raw units; scale folded into exp) ----
        if (jt >= 2*qx) {
            const int row_a = q0 + r0l, row_b = row_a + 8;
            #pragma unroll
            for (int j = 0; j < 8; ++j) {
                int col = k0 + j*8 + 2*(lane & 3);
                if (col     > row_a) s[j][0] = -1e30f;
                if (col + 1 > row_a) s[j][1] = -1e30f;
                if (col     > row_b) s[j][2] = -1e30f;
                if (col + 1 > row_b) s[j][3] = -1e30f;
            }
        }

        // ---- online softmax ----
        float mx0 = -1e30f, mx1 = -1e30f;
        #pragma unroll
        for (int j = 0; j < 8; ++j) {
            mx0 = fmaxf(mx0, fmaxf(s[j][0], s[j][1]));
            mx1 = fmaxf(mx1, fmaxf(s[j][2], s[j][3]));
        }
        #pragma unroll
        for (int off = 1; off <= 2; off <<= 1) {
            mx0 = fmaxf(mx0, __shfl_xor_sync(0xffffffffu, mx0, off));
            mx1 = fmaxf(mx1, __shfl_xor_sync(0xffffffffu, mx1, off));
        }
        float mn0 = fmaxf(m0, mx0), mn1 = fmaxf(m1, mx1);
        float al0 = __expf((m0 - mn0)*sc), al1 = __expf((m1 - mn1)*sc);
        m0 = mn0; m1 = mn1;
        float rs0 = 0.f, rs1 = 0.f;
        #pragma unroll
        for (int j = 0; j < 8; ++j) {
            s[j][0] = __expf((s[j][0] - mn0)*sc); rs0 += s[j][0];
            s[j][1] = __expf((s[j][1] - mn0)*sc); rs0 += s[j][1];
            s[j][2] = __expf((s[j][2] - mn1)*sc); rs1 += s[j][2];
            s[j][3] = __expf((s[j][3] - mn1)*sc); rs1 += s[j][3];
        }
        #pragma unroll
        for (int off = 1; off <= 2; off <<= 1) {
            rs0 += __shfl_xor_sync(0xffffffffu, rs0, off);
            rs1 += __shfl_xor_sync(0xffffffffu, rs1, off);
        }
        l0 = l0*al0 + rs0;
        l1 = l1*al1 + rs1;

        // ---- O = O*alpha + P @ V (P fragments via shuffle, no smem) ----
        #pragma unroll
        for (int j = 0; j < 8; ++j) {
            o[j][0] *= al0; o[j][1] *= al0;
            o[j][2] *= al1; o[j][3] *= al1;
        }
        #pragma unroll
        for (int kb = 0; kb < 8; ++kb) {
            // convert S-accumulator tile kb -> A-fragment for PV
            float v0 = __shfl_sync(0xffffffffu, s[kb][0], src0);
            float v1 = __shfl_sync(0xffffffffu, s[kb][1], src0);
            float v2 = __shfl_sync(0xffffffffu, s[kb][2], src0);
            float v3 = __shfl_sync(0xffffffffu, s[kb][3], src0);
            float w0 = __shfl_sync(0xffffffffu, s[kb][0], src1);
            float w1 = __shfl_sync(0xffffffffu, s[kb][1], src1);
            float w2 = __shfl_sync(0xffffffffu, s[kb][2], src1);
            float w3 = __shfl_sync(0xffffffffu, s[kb][3], src1);
            unsigned ap[4];
            ap[0] = __float_as_uint(oddl ? v1 : v0);
            ap[1] = __float_as_uint(oddl ? v3 : v2);
            ap[2] = __float_as_uint(oddl ? w1 : w0);
            ap[3] = __float_as_uint(oddl ? w3 : w2);
            const int kk = kb*8;
            #pragma unroll
            for (int j = 0; j < 8; ++j) {
                unsigned bv[2];
                bv[0] = __float_as_uint(vs_[(kk + (lane & 3)    )*VSTR + j*8 + (lane >> 2)]);
                bv[1] = __float_as_uint(vs_[(kk + (lane & 3) + 4)*VSTR + j*8 + (lane >> 2)]);
                mma_tf32(o[j], ap, bv);
            }
        }
        __syncthreads();                // reads of stage (jt+1)&1 done before next issue
    }

    // ---- epilogue ----
    const float inv0 = 1.f / l0, inv1 = 1.f / l1;
    const int grow = q0 + r0l;
    #pragma unroll
    for (int j = 0; j < 8; ++j) {
        int cc = j*8 + 2*(lane & 3);
        *(float2*)(out + base + (size_t)grow*DM + cc) =
            make_float2(o[j][0]*inv0, o[j][1]*inv0);
        *(float2*)(out + base + (size_t)(grow + 8)*DM + cc) =
            make_float2(o[j][2]*inv1, o[j][3]*inv1);
    }
}

// ---------------------------------------------------------------------------
// SiLU(gate) * up
// ---------------------------------------------------------------------------
__global__ void silu_mul_kernel(float* __restrict__ g, const float* __restrict__ u, int n4) {
    int i = blockIdx.x*blockDim.x + threadIdx.x;
    int stride = gridDim.x*blockDim.x;
    float4* g4 = (float4*)g;
    const float4* u4 = (const float4*)u;
    for (; i < n4; i += stride) {
        float4 gv = g4[i];
        float4 uv = u4[i];
        gv.x = gv.x / (1.f + __expf(-gv.x)) * uv.x;
        gv.y = gv.y / (1.f + __expf(-gv.y)) * uv.y;
        gv.z = gv.z / (1.f + __expf(-gv.z)) * uv.z;
        gv.w = gv.w / (1.f + __expf(-gv.w)) * uv.w;
        g4[i] = gv;
    }
}

// ---------------------------------------------------------------------------
// Launch
// ---------------------------------------------------------------------------
extern "C" void kernel_launch(void* const* d_in, const int* in_sizes, int n_in,
                              void* d_out, int out_size) {
    const float* x        = (const float*)d_in[0];
    const float* rms_attn = (const float*)d_in[2];
    const float* wq       = (const float*)d_in[3];
    const float* wk       = (const float*)d_in[4];
    const float* wv       = (const float*)d_in[5];
    const float* wo       = (const float*)d_in[6];
    const float* rms_ffn  = (const float*)d_in[7];
    const float* w_gate   = (const float*)d_in[8];
    const float* w_up     = (const float*)d_in[9];
    const float* w_down   = (const float*)d_in[10];
    float* out = (float*)d_out;

    float *h, *q, *k, *v, *attn, *x1, *hf, *gate, *up;
    cudaGetSymbolAddress((void**)&h,    g_h);
    cudaGetSymbolAddress((void**)&q,    g_q);
    cudaGetSymbolAddress((void**)&k,    g_k);
    cudaGetSymbolAddress((void**)&v,    g_v);
    cudaGetSymbolAddress((void**)&attn, g_attn);
    cudaGetSymbolAddress((void**)&x1,   g_x1);
    cudaGetSymbolAddress((void**)&hf,   g_hf);
    cudaGetSymbolAddress((void**)&gate, g_gate);
    cudaGetSymbolAddress((void**)&up,   g_up);

    const int GS128 = 3*(128 + 128)*TSTR*4;                        // 110592
    const int GS64  = 3*(128 +  64)*TSTR*4;                        // 82944
    const int ASM   = (128*QSTR + 2*64*KSTR + 2*64*VSTR)*4;        // 106496
    cudaFuncSetAttribute(gemm_mma<128>, cudaFuncAttributeMaxDynamicSharedMemorySize, GS128);
    cudaFuncSetAttribute(gemm_mma<64>,  cudaFuncAttributeMaxDynamicSharedMemorySize, GS64);
    cudaFuncSetAttribute(attn_mma,      cudaFuncAttributeMaxDynamicSharedMemorySize, ASM);

    // 1. h = rmsnorm(x)
    rmsnorm_kernel<<<BT, 256>>>(h, x, rms_attn);

    // 2. fused q,k,v projections
    gemm_mma<128><<<dim3(DM/128, BT/128, 3), 256, GS128>>>(
        h, wq, wk, wv, q, k, v, nullptr, BT, DM, DM);

    // 3. attention
    attn_mma<<<dim3(BB*NH, TT/128), 256, ASM>>>(attn, q, k, v);

    // 4. x1 = x + attn @ wo^T
    gemm_mma<64><<<dim3(DM/64, BT/128, 1), 256, GS64>>>(
        attn, wo, wo, wo, x1, x1, x1, x, BT, DM, DM);

    // 5. hf = rmsnorm(x1)
    rmsnorm_kernel<<<BT, 256>>>(hf, x1, rms_ffn);

    // 6. fused gate/up
    gemm_mma<128><<<dim3(DFF/128, BT/128, 2), 256, GS128>>>(
        hf, w_gate, w_up, w_up, gate, up, up, nullptr, BT, DFF, DM);

    // 7. gate = silu(gate)*up
    silu_mul_kernel<<<2048, 256>>>(gate, up, BT*DFF/4);

    // 8. out = x1 + gate @ w_down^T
    gemm_mma<64><<<dim3(DM/64, BT/128, 1), 256, GS64>>>(
        gate, w_down, w_down, w_down, out, out, out, x1, BT, DM, DFF);
}

// round 8
// speedup vs baseline: 4.1377x; 1.1772x over previous
#include <cuda_runtime.h>
#include <cuda_bf16.h>
#include <math.h>

// ---------------------------------------------------------------------------
// Problem constants
// ---------------------------------------------------------------------------
#define BB     4
#define TT     2048
#define DM     256
#define DFF    1024
#define NH     4
#define DK     64
#define BT     (BB*TT)          // 8192 rows

// ---------------------------------------------------------------------------
// Scratch
// ---------------------------------------------------------------------------
__device__ float g_h   [BT*DM];
__device__ float g_q   [BT*DM];
__device__ float g_k   [BT*DM];
__device__ float g_v   [BT*DM];
__device__ float g_attn[BT*DM];
__device__ float g_x1  [BT*DM];
__device__ float g_hf  [BT*DM];
__device__ float g_gate[BT*DFF];

// ---------------------------------------------------------------------------
// helpers
// ---------------------------------------------------------------------------
__device__ __forceinline__ void mma_tf32(float* c, const unsigned* a, const unsigned* b) {
    asm volatile(
        "mma.sync.aligned.m16n8k8.row.col.f32.tf32.tf32.f32 "
        "{%0,%1,%2,%3}, {%4,%5,%6,%7}, {%8,%9}, {%0,%1,%2,%3};\n"
        : "+f"(c[0]), "+f"(c[1]), "+f"(c[2]), "+f"(c[3])
        : "r"(a[0]), "r"(a[1]), "r"(a[2]), "r"(a[3]), "r"(b[0]), "r"(b[1]));
}

__device__ __forceinline__ void cpa16(float* s, const float* g) {
    unsigned sa = (unsigned)__cvta_generic_to_shared(s);
    asm volatile("cp.async.cg.shared.global [%0], [%1], 16;" :: "r"(sa), "l"(g));
}
__device__ __forceinline__ void cp_commit() { asm volatile("cp.async.commit_group;"); }
template<int N> __device__ __forceinline__ void cp_wait() {
    asm volatile("cp.async.wait_group %0;" :: "n"(N));
}

// ---------------------------------------------------------------------------
// RMSNorm
// ---------------------------------------------------------------------------
__global__ void rmsnorm_kernel(float* __restrict__ out, const float* __restrict__ x,
                               const float* __restrict__ w) {
    int row = blockIdx.x;
    int tid = threadIdx.x;
    float vx = x[row*DM + tid];
    float ss = vx*vx;
    #pragma unroll
    for (int off = 16; off >= 1; off >>= 1) ss += __shfl_xor_sync(0xffffffffu, ss, off);
    __shared__ float ws[8];
    if ((tid & 31) == 0) ws[tid >> 5] = ss;
    __syncthreads();
    float tot = ws[0];
    #pragma unroll
    for (int i = 1; i < 8; ++i) tot += ws[i];
    float rinv = rsqrtf(tot * (1.0f/DM) + 1e-5f);
    out[row*DM + tid] = vx * rinv * w[tid];
}

// ---------------------------------------------------------------------------
// Tensor-core GEMM (tf32): C[M,N] = A[M,K] @ Bw[N,K]^T (+res)
// 128 x BN_ tile, BK=32, 3-stage cp.async pipeline, 8 warps (4x2)
// ---------------------------------------------------------------------------
#define TSTR 36

template<int BN_>
__global__ __launch_bounds__(256, 2)
void gemm_mma(const float* __restrict__ A,
              const float* __restrict__ B0, const float* __restrict__ B1,
              const float* __restrict__ B2,
              float* __restrict__ C0, float* __restrict__ C1, float* __restrict__ C2,
              const float* __restrict__ res,
              int M, int N, int K) {
    constexpr int WN  = BN_/16;
    constexpr int ASZ = 128*TSTR;
    constexpr int BSZ = BN_*TSTR;
    extern __shared__ float smf[];
    float* As = smf;                  // 3 stages
    float* Bs = smf + 3*ASZ;

    const float* Bw = (blockIdx.z == 0) ? B0 : (blockIdx.z == 1 ? B1 : B2);
    float*       C  = (blockIdx.z == 0) ? C0 : (blockIdx.z == 1 ? C1 : C2);

    const int tid = threadIdx.x, lane = tid & 31, wid = tid >> 5;
    const int wrow = wid >> 1, wcol = wid & 1;
    const int row0 = blockIdx.y * 128;
    const int col0 = blockIdx.x * BN_;

    float acc[2][WN][4];
    #pragma unroll
    for (int i = 0; i < 2; ++i)
        #pragma unroll
        for (int j = 0; j < WN; ++j)
            #pragma unroll
            for (int t = 0; t < 4; ++t) acc[i][j][t] = 0.f;

    auto load_stage = [&](int k0, int st) {
        float* as = As + st*ASZ;
        float* bs = Bs + st*BSZ;
        #pragma unroll
        for (int it = 0; it < 4; ++it) {
            int idx = it*256 + tid, r = idx >> 3, c4 = (idx & 7)*4;
            cpa16(as + r*TSTR + c4, A + (size_t)(row0 + r)*K + k0 + c4);
        }
        #pragma unroll
        for (int it = 0; it < BN_/32; ++it) {
            int idx = it*256 + tid, r = idx >> 3, c4 = (idx & 7)*4;
            cpa16(bs + r*TSTR + c4, Bw + (size_t)(col0 + r)*K + k0 + c4);
        }
        cp_commit();
    };

    const int nt = K / 32;
    load_stage(0, 0);
    load_stage(32, 1);
    for (int t = 0; t < nt; ++t) {
        if (t + 2 < nt)      { load_stage((t+2)*32, (t+2) % 3); cp_wait<2>(); }
        else if (t + 1 < nt) { cp_wait<1>(); }
        else                 { cp_wait<0>(); }
        __syncthreads();
        const float* as = As + (t % 3)*ASZ;
        const float* bs = Bs + (t % 3)*BSZ;
        #pragma unroll
        for (int ks = 0; ks < 4; ++ks) {
            const int k = ks*8;
            unsigned a[2][4], b[WN][2];
            #pragma unroll
            for (int i = 0; i < 2; ++i) {
                int r = wrow*32 + i*16 + (lane >> 2);
                a[i][0] = __float_as_uint(as[ r     *TSTR + k + (lane & 3)    ]);
                a[i][1] = __float_as_uint(as[(r + 8)*TSTR + k + (lane & 3)    ]);
                a[i][2] = __float_as_uint(as[ r     *TSTR + k + (lane & 3) + 4]);
                a[i][3] = __float_as_uint(as[(r + 8)*TSTR + k + (lane & 3) + 4]);
            }
            #pragma unroll
            for (int j = 0; j < WN; ++j) {
                int n = wcol*(BN_/2) + j*8 + (lane >> 2);
                b[j][0] = __float_as_uint(bs[n*TSTR + k + (lane & 3)    ]);
                b[j][1] = __float_as_uint(bs[n*TSTR + k + (lane & 3) + 4]);
            }
            #pragma unroll
            for (int i = 0; i < 2; ++i)
                #pragma unroll
                for (int j = 0; j < WN; ++j)
                    mma_tf32(acc[i][j], a[i], b[j]);
        }
        __syncthreads();
    }

    #pragma unroll
    for (int i = 0; i < 2; ++i) {
        int r = row0 + wrow*32 + i*16 + (lane >> 2);
        #pragma unroll
        for (int j = 0; j < WN; ++j) {
            int c = col0 + wcol*(BN_/2) + j*8 + (lane & 3)*2;
            float2 v01 = { acc[i][j][0], acc[i][j][1] };
            float2 v23 = { acc[i][j][2], acc[i][j][3] };
            if (res) {
                float2 r01 = *(const float2*)(res + (size_t)r*N + c);
                float2 r23 = *(const float2*)(res + (size_t)(r+8)*N + c);
                v01.x += r01.x; v01.y += r01.y;
                v23.x += r23.x; v23.y += r23.y;
            }
            *(float2*)(C + (size_t)r*N + c)     = v01;
            *(float2*)(C + (size_t)(r+8)*N + c) = v23;
        }
    }
}

// ---------------------------------------------------------------------------
// Fused gate/up GEMM + SiLU: g = silu(A@Wg^T) * (A@Wu^T)
// 128 x 64 tile, two B operands, 3-stage pipeline, epilogue silu-mul
// ---------------------------------------------------------------------------
__global__ __launch_bounds__(256, 2)
void gemm_gateup(const float* __restrict__ A,
                 const float* __restrict__ Wg, const float* __restrict__ Wu,
                 float* __restrict__ G, int M, int N, int K) {
    constexpr int ASZ = 128*TSTR;
    constexpr int BSZ = 64*TSTR;
    extern __shared__ float smf[];
    float* As = smf;                  // 3 stages
    float* Gs = smf + 3*ASZ;
    float* Us = Gs + 3*BSZ;

    const int tid = threadIdx.x, lane = tid & 31, wid = tid >> 5;
    const int wrow = wid >> 1, wcol = wid & 1;
    const int row0 = blockIdx.y * 128;
    const int col0 = blockIdx.x * 64;

    float accg[2][4][4], accu[2][4][4];
    #pragma unroll
    for (int i = 0; i < 2; ++i)
        #pragma unroll
        for (int j = 0; j < 4; ++j)
            #pragma unroll
            for (int t = 0; t < 4; ++t) { accg[i][j][t] = 0.f; accu[i][j][t] = 0.f; }

    auto load_stage = [&](int k0, int st) {
        float* as = As + st*ASZ;
        float* gs = Gs + st*BSZ;
        float* us = Us + st*BSZ;
        #pragma unroll
        for (int it = 0; it < 4; ++it) {
            int idx = it*256 + tid, r = idx >> 3, c4 = (idx & 7)*4;
            cpa16(as + r*TSTR + c4, A + (size_t)(row0 + r)*K + k0 + c4);
        }
        #pragma unroll
        for (int it = 0; it < 2; ++it) {
            int idx = it*256 + tid, r = idx >> 3, c4 = (idx & 7)*4;
            cpa16(gs + r*TSTR + c4, Wg + (size_t)(col0 + r)*K + k0 + c4);
            cpa16(us + r*TSTR + c4, Wu + (size_t)(col0 + r)*K + k0 + c4);
        }
        cp_commit();
    };

    const int nt = K / 32;
    load_stage(0, 0);
    load_stage(32, 1);
    for (int t = 0; t < nt; ++t) {
        if (t + 2 < nt)      { load_stage((t+2)*32, (t+2) % 3); cp_wait<2>(); }
        else if (t + 1 < nt) { cp_wait<1>(); }
        else                 { cp_wait<0>(); }
        __syncthreads();
        const float* as = As + (t % 3)*ASZ;
        const float* gs = Gs + (t % 3)*BSZ;
        const float* us = Us + (t % 3)*BSZ;
        #pragma unroll
        for (int ks = 0; ks < 4; ++ks) {
            const int k = ks*8;
            unsigned a[2][4], bg[4][2], bu[4][2];
            #pragma unroll
            for (int i = 0; i < 2; ++i) {
                int r = wrow*32 + i*16 + (lane >> 2);
                a[i][0] = __float_as_uint(as[ r     *TSTR + k + (lane & 3)    ]);
                a[i][1] = __float_as_uint(as[(r + 8)*TSTR + k + (lane & 3)    ]);
                a[i][2] = __float_as_uint(as[ r     *TSTR + k + (lane & 3) + 4]);
                a[i][3] = __float_as_uint(as[(r + 8)*TSTR + k + (lane & 3) + 4]);
            }
            #pragma unroll
            for (int j = 0; j < 4; ++j) {
                int n = wcol*32 + j*8 + (lane >> 2);
                bg[j][0] = __float_as_uint(gs[n*TSTR + k + (lane & 3)    ]);
                bg[j][1] = __float_as_uint(gs[n*TSTR + k + (lane & 3) + 4]);
                bu[j][0] = __float_as_uint(us[n*TSTR + k + (lane & 3)    ]);
                bu[j][1] = __float_as_uint(us[n*TSTR + k + (lane & 3) + 4]);
            }
            #pragma unroll
            for (int i = 0; i < 2; ++i)
                #pragma unroll
                for (int j = 0; j < 4; ++j) {
                    mma_tf32(accg[i][j], a[i], bg[j]);
                    mma_tf32(accu[i][j], a[i], bu[j]);
                }
        }
        __syncthreads();
    }

    #pragma unroll
    for (int i = 0; i < 2; ++i) {
        int r = row0 + wrow*32 + i*16 + (lane >> 2);
        #pragma unroll
        for (int j = 0; j < 4; ++j) {
            int c = col0 + wcol*32 + j*8 + (lane & 3)*2;
            float g0 = accg[i][j][0], g1 = accg[i][j][1];
            float g2 = accg[i][j][2], g3 = accg[i][j][3];
            float2 v01, v23;
            v01.x = g0 / (1.f + __expf(-g0)) * accu[i][j][0];
            v01.y = g1 / (1.f + __expf(-g1)) * accu[i][j][1];
            v23.x = g2 / (1.f + __expf(-g2)) * accu[i][j][2];
            v23.y = g3 / (1.f + __expf(-g3)) * accu[i][j][3];
            *(float2*)(G + (size_t)r*N + c)     = v01;
            *(float2*)(G + (size_t)(r+8)*N + c) = v23;
        }
    }
}

// ---------------------------------------------------------------------------
// Tensor-core flash attention, balanced pairing:
// block = 128 threads (4 warps), one (b,h), processes q-tiles p and 31-p
// (64 rows each) sequentially => constant 33 KV tiles per block.
// ---------------------------------------------------------------------------
#define QSTR 68
#define KSTR 68
#define VSTR 72

__global__ __launch_bounds__(128, 2)
void attn_mma(float* __restrict__ out, const float* __restrict__ q,
              const float* __restrict__ k, const float* __restrict__ v) {
    extern __shared__ float smf[];
    float* Qs = smf;                    // 64 x QSTR
    float* Ks = Qs + 64*QSTR;           // 2 stages of 64 x KSTR
    float* Vs = Ks + 2*64*KSTR;         // 2 stages of 64 x VSTR

    const int tid = threadIdx.x, lane = tid & 31, wid = tid >> 5;
    const int bh = blockIdx.x;
    const int b = bh >> 2, h = bh & 3;
    const size_t base = (size_t)b*TT*DM + (size_t)h*DK;

    const int r0l = wid*16 + (lane >> 2);          // local q-row in [0,64)
    const int src0 = (lane & ~3) | ((lane & 3) >> 1);
    const int src1 = src0 + 2;
    const bool oddl = lane & 1;
    const float sc = 0.125f;

    auto load_kv = [&](int jt, int st) {
        const int k0 = jt*64;
        float* ks_ = Ks + st*64*KSTR;
        float* vs_ = Vs + st*64*VSTR;
        #pragma unroll
        for (int it = 0; it < 8; ++it) {
            int idx = it*128 + tid, r = idx >> 4, c4 = (idx & 15)*4;
            cpa16(ks_ + r*KSTR + c4, k + base + (size_t)(k0 + r)*DM + c4);
            cpa16(vs_ + r*VSTR + c4, v + base + (size_t)(k0 + r)*DM + c4);
        }
        cp_commit();
    };

    #pragma unroll
    for (int phase = 0; phase < 2; ++phase) {
        const int qx = phase == 0 ? blockIdx.y : 31 - blockIdx.y;   // 0..31
        const int q0 = qx * 64;
        const int ntile = qx + 1;

        // Q tile (own cp.async group), then first KV stage
        #pragma unroll
        for (int it = 0; it < 8; ++it) {
            int idx = it*128 + tid, r = idx >> 4, c4 = (idx & 15)*4;
            cpa16(Qs + r*QSTR + c4, q + base + (size_t)(q0 + r)*DM + c4);
        }
        cp_commit();
        load_kv(0, 0);

        float o[8][4];
        #pragma unroll
        for (int j = 0; j < 8; ++j)
            #pragma unroll
            for (int t = 0; t < 4; ++t) o[j][t] = 0.f;
        float m0 = -1e30f, m1 = -1e30f, l0 = 0.f, l1 = 0.f;

        for (int jt = 0; jt < ntile; ++jt) {
            if (jt + 1 < ntile) { load_kv(jt+1, (jt+1) & 1); cp_wait<1>(); }
            else                { cp_wait<0>(); }
            __syncthreads();
            const float* ks_ = Ks + (jt & 1)*64*KSTR;
            const float* vs_ = Vs + (jt & 1)*64*VSTR;
            const int k0 = jt*64;

            // ---- S = Q @ K^T ----
            float s[8][4];
            #pragma unroll
            for (int j = 0; j < 8; ++j)
                #pragma unroll
                for (int t = 0; t < 4; ++t) s[j][t] = 0.f;
            #pragma unroll
            for (int ks = 0; ks < 8; ++ks) {
                const int kk = ks*8;
                unsigned aq[4];
                aq[0] = __float_as_uint(Qs[ r0l     *QSTR + kk + (lane & 3)    ]);
                aq[1] = __float_as_uint(Qs[(r0l + 8)*QSTR + kk + (lane & 3)    ]);
                aq[2] = __float_as_uint(Qs[ r0l     *QSTR + kk + (lane & 3) + 4]);
                aq[3] = __float_as_uint(Qs[(r0l + 8)*QSTR + kk + (lane & 3) + 4]);
                #pragma unroll
                for (int j = 0; j < 8; ++j) {
                    unsigned bv[2];
                    int n = j*8 + (lane >> 2);
                    bv[0] = __float_as_uint(ks_[n*KSTR + kk + (lane & 3)    ]);
                    bv[1] = __float_as_uint(ks_[n*KSTR + kk + (lane & 3) + 4]);
                    mma_tf32(s[j], aq, bv);
                }
            }

            // ---- causal mask (only the diagonal tile) ----
            if (jt == ntile - 1) {
                const int row_a = q0 + r0l, row_b = row_a + 8;
                #pragma unroll
                for (int j = 0; j < 8; ++j) {
                    int col = k0 + j*8 + 2*(lane & 3);
                    if (col     > row_a) s[j][0] = -1e30f;
                    if (col + 1 > row_a) s[j][1] = -1e30f;
                    if (col     > row_b) s[j][2] = -1e30f;
                    if (col + 1 > row_b) s[j][3] = -1e30f;
                }
            }

            // ---- online softmax ----
            float mx0 = -1e30f, mx1 = -1e30f;
            #pragma unroll
            for (int j = 0; j < 8; ++j) {
                mx0 = fmaxf(mx0, fmaxf(s[j][0], s[j][1]));
                mx1 = fmaxf(mx1, fmaxf(s[j][2], s[j][3]));
            }
            #pragma unroll
            for (int off = 1; off <= 2; off <<= 1) {
                mx0 = fmaxf(mx0, __shfl_xor_sync(0xffffffffu, mx0, off));
                mx1 = fmaxf(mx1, __shfl_xor_sync(0xffffffffu, mx1, off));
            }
            float mn0 = fmaxf(m0, mx0), mn1 = fmaxf(m1, mx1);
            float al0 = __expf((m0 - mn0)*sc), al1 = __expf((m1 - mn1)*sc);
            m0 = mn0; m1 = mn1;
            float rs0 = 0.f, rs1 = 0.f;
            #pragma unroll
            for (int j = 0; j < 8; ++j) {
                s[j][0] = __expf((s[j][0] - mn0)*sc); rs0 += s[j][0];
                s[j][1] = __expf((s[j][1] - mn0)*sc); rs0 += s[j][1];
                s[j][2] = __expf((s[j][2] - mn1)*sc); rs1 += s[j][2];
                s[j][3] = __expf((s[j][3] - mn1)*sc); rs1 += s[j][3];
            }
            #pragma unroll
            for (int off = 1; off <= 2; off <<= 1) {
                rs0 += __shfl_xor_sync(0xffffffffu, rs0, off);
                rs1 += __shfl_xor_sync(0xffffffffu, rs1, off);
            }
            l0 = l0*al0 + rs0;
            l1 = l1*al1 + rs1;

            // ---- O = O*alpha + P @ V (shuffle conversion) ----
            #pragma unroll
            for (int j = 0; j < 8; ++j) {
                o[j][0] *= al0; o[j][1] *= al0;
                o[j][2] *= al1; o[j][3] *= al1;
            }
            #pragma unroll
            for (int kb = 0; kb < 8; ++kb) {
                float v0 = __shfl_sync(0xffffffffu, s[kb][0], src0);
                float v1 = __shfl_sync(0xffffffffu, s[kb][1], src0);
                float v2 = __shfl_sync(0xffffffffu, s[kb][2], src0);
                float v3 = __shfl_sync(0xffffffffu, s[kb][3], src0);
                float w0 = __shfl_sync(0xffffffffu, s[kb][0], src1);
                float w1 = __shfl_sync(0xffffffffu, s[kb][1], src1);
                float w2 = __shfl_sync(0xffffffffu, s[kb][2], src1);
                float w3 = __shfl_sync(0xffffffffu, s[kb][3], src1);
                unsigned ap[4];
                ap[0] = __float_as_uint(oddl ? v1 : v0);
                ap[1] = __float_as_uint(oddl ? v3 : v2);
                ap[2] = __float_as_uint(oddl ? w1 : w0);
                ap[3] = __float_as_uint(oddl ? w3 : w2);
                const int kk = kb*8;
                #pragma unroll
                for (int j = 0; j < 8; ++j) {
                    unsigned bv[2];
                    bv[0] = __float_as_uint(vs_[(kk + (lane & 3)    )*VSTR + j*8 + (lane >> 2)]);
                    bv[1] = __float_as_uint(vs_[(kk + (lane & 3) + 4)*VSTR + j*8 + (lane >> 2)]);
                    mma_tf32(o[j], ap, bv);
                }
            }
            __syncthreads();
        }

        // ---- epilogue ----
        const float inv0 = 1.f / l0, inv1 = 1.f / l1;
        const int grow = q0 + r0l;
        #pragma unroll
        for (int j = 0; j < 8; ++j) {
            int cc = j*8 + 2*(lane & 3);
            *(float2*)(out + base + (size_t)grow*DM + cc) =
                make_float2(o[j][0]*inv0, o[j][1]*inv0);
            *(float2*)(out + base + (size_t)(grow + 8)*DM + cc) =
                make_float2(o[j][2]*inv1, o[j][3]*inv1);
        }
    }
}

// ---------------------------------------------------------------------------
// Launch
// ---------------------------------------------------------------------------
extern "C" void kernel_launch(void* const* d_in, const int* in_sizes, int n_in,
                              void* d_out, int out_size) {
    const float* x        = (const float*)d_in[0];
    const float* rms_attn = (const float*)d_in[2];
    const float* wq       = (const float*)d_in[3];
    const float* wk       = (const float*)d_in[4];
    const float* wv       = (const float*)d_in[5];
    const float* wo       = (const float*)d_in[6];
    const float* rms_ffn  = (const float*)d_in[7];
    const float* w_gate   = (const float*)d_in[8];
    const float* w_up     = (const float*)d_in[9];
    const float* w_down   = (const float*)d_in[10];
    float* out = (float*)d_out;

    float *h, *q, *k, *v, *attn, *x1, *hf, *gate;
    cudaGetSymbolAddress((void**)&h,    g_h);
    cudaGetSymbolAddress((void**)&q,    g_q);
    cudaGetSymbolAddress((void**)&k,    g_k);
    cudaGetSymbolAddress((void**)&v,    g_v);
    cudaGetSymbolAddress((void**)&attn, g_attn);
    cudaGetSymbolAddress((void**)&x1,   g_x1);
    cudaGetSymbolAddress((void**)&hf,   g_hf);
    cudaGetSymbolAddress((void**)&gate, g_gate);

    const int GS128 = 3*(128 + 128)*TSTR*4;                        // 110592
    const int GS64  = 3*(128 +  64)*TSTR*4;                        // 82944
    const int GSGU  = 3*(128 + 64 + 64)*TSTR*4;                    // 110592
    const int ASM   = (64*QSTR + 2*64*KSTR + 2*64*VSTR)*4;         // 89088
    cudaFuncSetAttribute(gemm_mma<128>, cudaFuncAttributeMaxDynamicSharedMemorySize, GS128);
    cudaFuncSetAttribute(gemm_mma<64>,  cudaFuncAttributeMaxDynamicSharedMemorySize, GS64);
    cudaFuncSetAttribute(gemm_gateup,   cudaFuncAttributeMaxDynamicSharedMemorySize, GSGU);
    cudaFuncSetAttribute(attn_mma,      cudaFuncAttributeMaxDynamicSharedMemorySize, ASM);

    // 1. h = rmsnorm(x)
    rmsnorm_kernel<<<BT, 256>>>(h, x, rms_attn);

    // 2. fused q,k,v projections
    gemm_mma<128><<<dim3(DM/128, BT/128, 3), 256, GS128>>>(
        h, wq, wk, wv, q, k, v, nullptr, BT, DM, DM);

    // 3. attention (balanced pairing)
    attn_mma<<<dim3(BB*NH, 16), 128, ASM>>>(attn, q, k, v);

    // 4. x1 = x + attn @ wo^T
    gemm_mma<64><<<dim3(DM/64, BT/128, 1), 256, GS64>>>(
        attn, wo, wo, wo, x1, x1, x1, x, BT, DM, DM);

    // 5. hf = rmsnorm(x1)
    rmsnorm_kernel<<<BT, 256>>>(hf, x1, rms_ffn);

    // 6. fused gate/up/silu
    gemm_gateup<<<dim3(DFF/64, BT/128), 256, GSGU>>>(
        hf, w_gate, w_up, gate, BT, DFF, DM);

    // 7. out = x1 + gate @ w_down^T
    gemm_mma<64><<<dim3(DM/64, BT/128, 1), 256, GS64>>>(
        gate, w_down, w_down, w_down, out, out, out, x1, BT, DM, DFF);
}

// round 9
// speedup vs baseline: 4.1867x; 1.0118x over previous
#include <cuda_runtime.h>
#include <cuda_bf16.h>
#include <math.h>

// ---------------------------------------------------------------------------
// Problem constants
// ---------------------------------------------------------------------------
#define BB     4
#define TT     2048
#define DM     256
#define DFF    1024
#define NH     4
#define DK     64
#define BT     (BB*TT)          // 8192 rows

// ---------------------------------------------------------------------------
// Scratch
// ---------------------------------------------------------------------------
__device__ float g_h   [BT*DM];
__device__ float g_q   [BT*DM];
__device__ float g_k   [BT*DM];
__device__ float g_v   [BT*DM];
__device__ float g_attn[BT*DM];
__device__ float g_x1  [BT*DM];
__device__ float g_hf  [BT*DM];
__device__ float g_gate[BT*DFF];

// ---------------------------------------------------------------------------
// helpers
// ---------------------------------------------------------------------------
__device__ __forceinline__ void mma_tf32(float* c, const unsigned* a, const unsigned* b) {
    asm volatile(
        "mma.sync.aligned.m16n8k8.row.col.f32.tf32.tf32.f32 "
        "{%0,%1,%2,%3}, {%4,%5,%6,%7}, {%8,%9}, {%0,%1,%2,%3};\n"
        : "+f"(c[0]), "+f"(c[1]), "+f"(c[2]), "+f"(c[3])
        : "r"(a[0]), "r"(a[1]), "r"(a[2]), "r"(a[3]), "r"(b[0]), "r"(b[1]));
}

// ldmatrix x4 on 32-bit data: returns the 4 m8x4(tf32) matrices whose row
// addresses are supplied by lane groups 0-7 / 8-15 / 16-23 / 24-31.
__device__ __forceinline__ void ldsm4(unsigned* r, const float* p) {
    unsigned a = (unsigned)__cvta_generic_to_shared(p);
    asm volatile("ldmatrix.sync.aligned.m8n8.x4.shared.b16 {%0,%1,%2,%3}, [%4];"
                 : "=r"(r[0]), "=r"(r[1]), "=r"(r[2]), "=r"(r[3]) : "r"(a));
}

__device__ __forceinline__ void cpa16(float* s, const float* g) {
    unsigned sa = (unsigned)__cvta_generic_to_shared(s);
    asm volatile("cp.async.cg.shared.global [%0], [%1], 16;" :: "r"(sa), "l"(g));
}
__device__ __forceinline__ void cp_commit() { asm volatile("cp.async.commit_group;"); }
template<int N> __device__ __forceinline__ void cp_wait() {
    asm volatile("cp.async.wait_group %0;" :: "n"(N));
}

// ---------------------------------------------------------------------------
// RMSNorm
// ---------------------------------------------------------------------------
__global__ void rmsnorm_kernel(float* __restrict__ out, const float* __restrict__ x,
                               const float* __restrict__ w) {
    int row = blockIdx.x;
    int tid = threadIdx.x;
    float vx = x[row*DM + tid];
    float ss = vx*vx;
    #pragma unroll
    for (int off = 16; off >= 1; off >>= 1) ss += __shfl_xor_sync(0xffffffffu, ss, off);
    __shared__ float ws[8];
    if ((tid & 31) == 0) ws[tid >> 5] = ss;
    __syncthreads();
    float tot = ws[0];
    #pragma unroll
    for (int i = 1; i < 8; ++i) tot += ws[i];
    float rinv = rsqrtf(tot * (1.0f/DM) + 1e-5f);
    out[row*DM + tid] = vx * rinv * w[tid];
}

// ---------------------------------------------------------------------------
// Tensor-core GEMM (tf32): C[M,N] = A[M,K] @ Bw[N,K]^T (+res)
// 128 x BN_ tile, BK=32, 3-stage cp.async pipeline, 8 warps (4x2), ldmatrix
// ---------------------------------------------------------------------------
#define TSTR 36

template<int BN_>
__global__ __launch_bounds__(256, 2)
void gemm_mma(const float* __restrict__ A,
              const float* __restrict__ B0, const float* __restrict__ B1,
              const float* __restrict__ B2,
              float* __restrict__ C0, float* __restrict__ C1, float* __restrict__ C2,
              const float* __restrict__ res,
              int M, int N, int K) {
    constexpr int WN  = BN_/16;
    constexpr int ASZ = 128*TSTR;
    constexpr int BSZ = BN_*TSTR;
    extern __shared__ float smf[];
    float* As = smf;                  // 3 stages
    float* Bs = smf + 3*ASZ;

    const float* Bw = (blockIdx.z == 0) ? B0 : (blockIdx.z == 1 ? B1 : B2);
    float*       C  = (blockIdx.z == 0) ? C0 : (blockIdx.z == 1 ? C1 : C2);

    const int tid = threadIdx.x, lane = tid & 31, wid = tid >> 5;
    const int wrow = wid >> 1, wcol = wid & 1;
    const int row0 = blockIdx.y * 128;
    const int col0 = blockIdx.x * BN_;

    // ldmatrix per-lane offsets
    const int aoff = ((lane & 7) + ((lane >> 3) & 1)*8)*TSTR + (lane >> 4)*4;
    const int boff = ((lane & 7) + (lane >> 4)*8)*TSTR + ((lane >> 3) & 1)*4;

    float acc[2][WN][4];
    #pragma unroll
    for (int i = 0; i < 2; ++i)
        #pragma unroll
        for (int j = 0; j < WN; ++j)
            #pragma unroll
            for (int t = 0; t < 4; ++t) acc[i][j][t] = 0.f;

    auto load_stage = [&](int k0, int st) {
        float* as = As + st*ASZ;
        float* bs = Bs + st*BSZ;
        #pragma unroll
        for (int it = 0; it < 4; ++it) {
            int idx = it*256 + tid, r = idx >> 3, c4 = (idx & 7)*4;
            cpa16(as + r*TSTR + c4, A + (size_t)(row0 + r)*K + k0 + c4);
        }
        #pragma unroll
        for (int it = 0; it < BN_/32; ++it) {
            int idx = it*256 + tid, r = idx >> 3, c4 = (idx & 7)*4;
            cpa16(bs + r*TSTR + c4, Bw + (size_t)(col0 + r)*K + k0 + c4);
        }
        cp_commit();
    };

    const int nt = K / 32;
    load_stage(0, 0);
    load_stage(32, 1);
    for (int t = 0; t < nt; ++t) {
        if (t + 2 < nt)      { load_stage((t+2)*32, (t+2) % 3); cp_wait<2>(); }
        else if (t + 1 < nt) { cp_wait<1>(); }
        else                 { cp_wait<0>(); }
        __syncthreads();
        const float* as = As + (t % 3)*ASZ + aoff + wrow*32*TSTR;
        const float* bs = Bs + (t % 3)*BSZ + boff + wcol*(BN_/2)*TSTR;
        #pragma unroll
        for (int ks = 0; ks < 4; ++ks) {
            const int k = ks*8;
            unsigned a[2][4], b[WN][2];
            #pragma unroll
            for (int i = 0; i < 2; ++i)
                ldsm4(a[i], as + i*16*TSTR + k);
            #pragma unroll
            for (int jp = 0; jp < WN/2; ++jp)
                ldsm4(&b[2*jp][0], bs + jp*16*TSTR + k);
            #pragma unroll
            for (int i = 0; i < 2; ++i)
                #pragma unroll
                for (int j = 0; j < WN; ++j)
                    mma_tf32(acc[i][j], a[i], b[j]);
        }
        __syncthreads();
    }

    #pragma unroll
    for (int i = 0; i < 2; ++i) {
        int r = row0 + wrow*32 + i*16 + (lane >> 2);
        #pragma unroll
        for (int j = 0; j < WN; ++j) {
            int c = col0 + wcol*(BN_/2) + j*8 + (lane & 3)*2;
            float2 v01 = { acc[i][j][0], acc[i][j][1] };
            float2 v23 = { acc[i][j][2], acc[i][j][3] };
            if (res) {
                float2 r01 = *(const float2*)(res + (size_t)r*N + c);
                float2 r23 = *(const float2*)(res + (size_t)(r+8)*N + c);
                v01.x += r01.x; v01.y += r01.y;
                v23.x += r23.x; v23.y += r23.y;
            }
            *(float2*)(C + (size_t)r*N + c)     = v01;
            *(float2*)(C + (size_t)(r+8)*N + c) = v23;
        }
    }
}

// ---------------------------------------------------------------------------
// Fused gate/up GEMM + SiLU: g = silu(A@Wg^T) * (A@Wu^T)
// ---------------------------------------------------------------------------
__global__ __launch_bounds__(256, 2)
void gemm_gateup(const float* __restrict__ A,
                 const float* __restrict__ Wg, const float* __restrict__ Wu,
                 float* __restrict__ G, int M, int N, int K) {
    constexpr int ASZ = 128*TSTR;
    constexpr int BSZ = 64*TSTR;
    extern __shared__ float smf[];
    float* As = smf;                  // 3 stages
    float* Gs = smf + 3*ASZ;
    float* Us = Gs + 3*BSZ;

    const int tid = threadIdx.x, lane = tid & 31, wid = tid >> 5;
    const int wrow = wid >> 1, wcol = wid & 1;
    const int row0 = blockIdx.y * 128;
    const int col0 = blockIdx.x * 64;

    const int aoff = ((lane & 7) + ((lane >> 3) & 1)*8)*TSTR + (lane >> 4)*4;
    const int boff = ((lane & 7) + (lane >> 4)*8)*TSTR + ((lane >> 3) & 1)*4;

    float accg[2][4][4], accu[2][4][4];
    #pragma unroll
    for (int i = 0; i < 2; ++i)
        #pragma unroll
        for (int j = 0; j < 4; ++j)
            #pragma unroll
            for (int t = 0; t < 4; ++t) { accg[i][j][t] = 0.f; accu[i][j][t] = 0.f; }

    auto load_stage = [&](int k0, int st) {
        float* as = As + st*ASZ;
        float* gs = Gs + st*BSZ;
        float* us = Us + st*BSZ;
        #pragma unroll
        for (int it = 0; it < 4; ++it) {
            int idx = it*256 + tid, r = idx >> 3, c4 = (idx & 7)*4;
            cpa16(as + r*TSTR + c4, A + (size_t)(row0 + r)*K + k0 + c4);
        }
        #pragma unroll
        for (int it = 0; it < 2; ++it) {
            int idx = it*256 + tid, r = idx >> 3, c4 = (idx & 7)*4;
            cpa16(gs + r*TSTR + c4, Wg + (size_t)(col0 + r)*K + k0 + c4);
            cpa16(us + r*TSTR + c4, Wu + (size_t)(col0 + r)*K + k0 + c4);
        }
        cp_commit();
    };

    const int nt = K / 32;
    load_stage(0, 0);
    load_stage(32, 1);
    for (int t = 0; t < nt; ++t) {
        if (t + 2 < nt)      { load_stage((t+2)*32, (t+2) % 3); cp_wait<2>(); }
        else if (t + 1 < nt) { cp_wait<1>(); }
        else                 { cp_wait<0>(); }
        __syncthreads();
        const float* as = As + (t % 3)*ASZ + aoff + wrow*32*TSTR;
        const float* gs = Gs + (t % 3)*BSZ + boff + wcol*32*TSTR;
        const float* us = Us + (t % 3)*BSZ + boff + wcol*32*TSTR;
        #pragma unroll
        for (int ks = 0; ks < 4; ++ks) {
            const int k = ks*8;
            unsigned a[2][4], bg[4][2], bu[4][2];
            #pragma unroll
            for (int i = 0; i < 2; ++i)
                ldsm4(a[i], as + i*16*TSTR + k);
            #pragma unroll
            for (int jp = 0; jp < 2; ++jp) {
                ldsm4(&bg[2*jp][0], gs + jp*16*TSTR + k);
                ldsm4(&bu[2*jp][0], us + jp*16*TSTR + k);
            }
            #pragma unroll
            for (int i = 0; i < 2; ++i)
                #pragma unroll
                for (int j = 0; j < 4; ++j) {
                    mma_tf32(accg[i][j], a[i], bg[j]);
                    mma_tf32(accu[i][j], a[i], bu[j]);
                }
        }
        __syncthreads();
    }

    #pragma unroll
    for (int i = 0; i < 2; ++i) {
        int r = row0 + wrow*32 + i*16 + (lane >> 2);
        #pragma unroll
        for (int j = 0; j < 4; ++j) {
            int c = col0 + wcol*32 + j*8 + (lane & 3)*2;
            float g0 = accg[i][j][0], g1 = accg[i][j][1];
            float g2 = accg[i][j][2], g3 = accg[i][j][3];
            float2 v01, v23;
            v01.x = g0 / (1.f + __expf(-g0)) * accu[i][j][0];
            v01.y = g1 / (1.f + __expf(-g1)) * accu[i][j][1];
            v23.x = g2 / (1.f + __expf(-g2)) * accu[i][j][2];
            v23.y = g3 / (1.f + __expf(-g3)) * accu[i][j][3];
            *(float2*)(G + (size_t)r*N + c)     = v01;
            *(float2*)(G + (size_t)(r+8)*N + c) = v23;
        }
    }
}

// ---------------------------------------------------------------------------
// Tensor-core flash attention, occupancy-4 variant:
// 512 blocks (16 bh x 32 q-tiles of 64 rows), 128 threads, single-buffered
// KV (53KB smem), heavy q-tiles launched first, ldmatrix Q/K fragments.
// ---------------------------------------------------------------------------
#define QSTR 68
#define KSTR 68
#define VSTR 72

__global__ __launch_bounds__(128, 4)
void attn_mma(float* __restrict__ out, const float* __restrict__ q,
              const float* __restrict__ k, const float* __restrict__ v) {
    extern __shared__ float smf[];
    float* Qs = smf;                    // 64 x QSTR
    float* Ks = Qs + 64*QSTR;           // 64 x KSTR
    float* Vs = Ks + 64*KSTR;           // 64 x VSTR

    const int tid = threadIdx.x, lane = tid & 31, wid = tid >> 5;
    const int bh = blockIdx.x;
    const int qx = 31 - blockIdx.y;                // heavy tiles first
    const int b = bh >> 2, h = bh & 3;
    const int q0 = qx * 64;
    const int ntile = qx + 1;
    const size_t base = (size_t)b*TT*DM + (size_t)h*DK;

    const int r0l = wid*16 + (lane >> 2);          // local q-row
    const int src0 = (lane & ~3) | ((lane & 3) >> 1);
    const int src1 = src0 + 2;
    const bool oddl = lane & 1;
    const float sc = 0.125f;

    const int aoffq = ((lane & 7) + ((lane >> 3) & 1)*8)*QSTR + (lane >> 4)*4;
    const int boffk = ((lane & 7) + (lane >> 4)*8)*KSTR + ((lane >> 3) & 1)*4;

    auto load_kv = [&](int jt) {
        const int k0 = jt*64;
        #pragma unroll
        for (int it = 0; it < 8; ++it) {
            int idx = it*128 + tid, r = idx >> 4, c4 = (idx & 15)*4;
            cpa16(Ks + r*KSTR + c4, k + base + (size_t)(k0 + r)*DM + c4);
            cpa16(Vs + r*VSTR + c4, v + base + (size_t)(k0 + r)*DM + c4);
        }
        cp_commit();
    };

    // Q tile + first KV
    #pragma unroll
    for (int it = 0; it < 8; ++it) {
        int idx = it*128 + tid, r = idx >> 4, c4 = (idx & 15)*4;
        cpa16(Qs + r*QSTR + c4, q + base + (size_t)(q0 + r)*DM + c4);
    }
    cp_commit();
    load_kv(0);

    float o[8][4];
    #pragma unroll
    for (int j = 0; j < 8; ++j)
        #pragma unroll
        for (int t = 0; t < 4; ++t) o[j][t] = 0.f;
    float m0 = -1e30f, m1 = -1e30f, l0 = 0.f, l1 = 0.f;

    for (int jt = 0; jt < ntile; ++jt) {
        cp_wait<0>();
        __syncthreads();
        const int k0 = jt*64;

        // ---- S = Q @ K^T ----
        float s[8][4];
        #pragma unroll
        for (int j = 0; j < 8; ++j)
            #pragma unroll
            for (int t = 0; t < 4; ++t) s[j][t] = 0.f;
        #pragma unroll
        for (int ks = 0; ks < 8; ++ks) {
            const int kk = ks*8;
            unsigned aq[4], bv[8][2];
            ldsm4(aq, Qs + wid*16*QSTR + aoffq + kk);
            #pragma unroll
            for (int jp = 0; jp < 4; ++jp)
                ldsm4(&bv[2*jp][0], Ks + jp*16*KSTR + boffk + kk);
            #pragma unroll
            for (int j = 0; j < 8; ++j)
                mma_tf32(s[j], aq, bv[j]);
        }

        // ---- causal mask (diagonal tile only) ----
        if (jt == ntile - 1) {
            const int row_a = q0 + r0l, row_b = row_a + 8;
            #pragma unroll
            for (int j = 0; j < 8; ++j) {
                int col = k0 + j*8 + 2*(lane & 3);
                if (col     > row_a) s[j][0] = -1e30f;
                if (col + 1 > row_a) s[j][1] = -1e30f;
                if (col     > row_b) s[j][2] = -1e30f;
                if (col + 1 > row_b) s[j][3] = -1e30f;
            }
        }

        // ---- online softmax ----
        float mx0 = -1e30f, mx1 = -1e30f;
        #pragma unroll
        for (int j = 0; j < 8; ++j) {
            mx0 = fmaxf(mx0, fmaxf(s[j][0], s[j][1]));
            mx1 = fmaxf(mx1, fmaxf(s[j][2], s[j][3]));
        }
        #pragma unroll
        for (int off = 1; off <= 2; off <<= 1) {
            mx0 = fmaxf(mx0, __shfl_xor_sync(0xffffffffu, mx0, off));
            mx1 = fmaxf(mx1, __shfl_xor_sync(0xffffffffu, mx1, off));
        }
        float mn0 = fmaxf(m0, mx0), mn1 = fmaxf(m1, mx1);
        float al0 = __expf((m0 - mn0)*sc), al1 = __expf((m1 - mn1)*sc);
        m0 = mn0; m1 = mn1;
        float rs0 = 0.f, rs1 = 0.f;
        #pragma unroll
        for (int j = 0; j < 8; ++j) {
            s[j][0] = __expf((s[j][0] - mn0)*sc); rs0 += s[j][0];
            s[j][1] = __expf((s[j][1] - mn0)*sc); rs0 += s[j][1];
            s[j][2] = __expf((s[j][2] - mn1)*sc); rs1 += s[j][2];
            s[j][3] = __expf((s[j][3] - mn1)*sc); rs1 += s[j][3];
        }
        #pragma unroll
        for (int off = 1; off <= 2; off <<= 1) {
            rs0 += __shfl_xor_sync(0xffffffffu, rs0, off);
            rs1 += __shfl_xor_sync(0xffffffffu, rs1, off);
        }
        l0 = l0*al0 + rs0;
        l1 = l1*al1 + rs1;

        // ---- O = O*alpha + P @ V (shuffle conversion) ----
        #pragma unroll
        for (int j = 0; j < 8; ++j) {
            o[j][0] *= al0; o[j][1] *= al0;
            o[j][2] *= al1; o[j][3] *= al1;
        }
        #pragma unroll
        for (int kb = 0; kb < 8; ++kb) {
            float v0 = __shfl_sync(0xffffffffu, s[kb][0], src0);
            float v1 = __shfl_sync(0xffffffffu, s[kb][1], src0);
            float v2 = __shfl_sync(0xffffffffu, s[kb][2], src0);
            float v3 = __shfl_sync(0xffffffffu, s[kb][3], src0);
            float w0 = __shfl_sync(0xffffffffu, s[kb][0], src1);
            float w1 = __shfl_sync(0xffffffffu, s[kb][1], src1);
            float w2 = __shfl_sync(0xffffffffu, s[kb][2], src1);
            float w3 = __shfl_sync(0xffffffffu, s[kb][3], src1);
            unsigned ap[4];
            ap[0] = __float_as_uint(oddl ? v1 : v0);
            ap[1] = __float_as_uint(oddl ? v3 : v2);
            ap[2] = __float_as_uint(oddl ? w1 : w0);
            ap[3] = __float_as_uint(oddl ? w3 : w2);
            const int kk = kb*8;
            #pragma unroll
            for (int j = 0; j < 8; ++j) {
                unsigned bv[2];
                bv[0] = __float_as_uint(Vs[(kk + (lane & 3)    )*VSTR + j*8 + (lane >> 2)]);
                bv[1] = __float_as_uint(Vs[(kk + (lane & 3) + 4)*VSTR + j*8 + (lane >> 2)]);
                mma_tf32(o[j], ap, bv);
            }
        }
        __syncthreads();                // all reads done before next overwrite
        if (jt + 1 < ntile) load_kv(jt + 1);
    }

    // ---- epilogue ----
    const float inv0 = 1.f / l0, inv1 = 1.f / l1;
    const int grow = q0 + r0l;
    #pragma unroll
    for (int j = 0; j < 8; ++j) {
        int cc = j*8 + 2*(lane & 3);
        *(float2*)(out + base + (size_t)grow*DM + cc) =
            make_float2(o[j][0]*inv0, o[j][1]*inv0);
        *(float2*)(out + base + (size_t)(grow + 8)*DM + cc) =
            make_float2(o[j][2]*inv1, o[j][3]*inv1);
    }
}

// ---------------------------------------------------------------------------
// Launch
// ---------------------------------------------------------------------------
extern "C" void kernel_launch(void* const* d_in, const int* in_sizes, int n_in,
                              void* d_out, int out_size) {
    const float* x        = (const float*)d_in[0];
    const float* rms_attn = (const float*)d_in[2];
    const float* wq       = (const float*)d_in[3];
    const float* wk       = (const float*)d_in[4];
    const float* wv       = (const float*)d_in[5];
    const float* wo       = (const float*)d_in[6];
    const float* rms_ffn  = (const float*)d_in[7];
    const float* w_gate   = (const float*)d_in[8];
    const float* w_up     = (const float*)d_in[9];
    const float* w_down   = (const float*)d_in[10];
    float* out = (float*)d_out;

    float *h, *q, *k, *v, *attn, *x1, *hf, *gate;
    cudaGetSymbolAddress((void**)&h,    g_h);
    cudaGetSymbolAddress((void**)&q,    g_q);
    cudaGetSymbolAddress((void**)&k,    g_k);
    cudaGetSymbolAddress((void**)&v,    g_v);
    cudaGetSymbolAddress((void**)&attn, g_attn);
    cudaGetSymbolAddress((void**)&x1,   g_x1);
    cudaGetSymbolAddress((void**)&hf,   g_hf);
    cudaGetSymbolAddress((void**)&gate, g_gate);

    const int GS128 = 3*(128 + 128)*TSTR*4;                        // 110592
    const int GS64  = 3*(128 +  64)*TSTR*4;                        // 82944
    const int GSGU  = 3*(128 + 64 + 64)*TSTR*4;                    // 110592
    const int ASM   = (64*QSTR + 64*KSTR + 64*VSTR)*4;             // 53248
    cudaFuncSetAttribute(gemm_mma<128>, cudaFuncAttributeMaxDynamicSharedMemorySize, GS128);
    cudaFuncSetAttribute(gemm_mma<64>,  cudaFuncAttributeMaxDynamicSharedMemorySize, GS64);
    cudaFuncSetAttribute(gemm_gateup,   cudaFuncAttributeMaxDynamicSharedMemorySize, GSGU);
    cudaFuncSetAttribute(attn_mma,      cudaFuncAttributeMaxDynamicSharedMemorySize, ASM);

    // 1. h = rmsnorm(x)
    rmsnorm_kernel<<<BT, 256>>>(h, x, rms_attn);

    // 2. fused q,k,v projections
    gemm_mma<128><<<dim3(DM/128, BT/128, 3), 256, GS128>>>(
        h, wq, wk, wv, q, k, v, nullptr, BT, DM, DM);

    // 3. attention (512 blocks, heavy-first, occ 4)
    attn_mma<<<dim3(BB*NH, 32), 128, ASM>>>(attn, q, k, v);

    // 4. x1 = x + attn @ wo^T
    gemm_mma<64><<<dim3(DM/64, BT/128, 1), 256, GS64>>>(
        attn, wo, wo, wo, x1, x1, x1, x, BT, DM, DM);

    // 5. hf = rmsnorm(x1)
    rmsnorm_kernel<<<BT, 256>>>(hf, x1, rms_ffn);

    // 6. fused gate/up/silu
    gemm_gateup<<<dim3(DFF/64, BT/128), 256, GSGU>>>(
        hf, w_gate, w_up, gate, BT, DFF, DM);

    // 7. out = x1 + gate @ w_down^T
    gemm_mma<64><<<dim3(DM/64, BT/128, 1), 256, GS64>>>(
        gate, w_down, w_down, w_down, out, out, out, x1, BT, DM, DFF);
}

// round 10
// speedup vs baseline: 6.9250x; 1.6541x over previous
#include <cuda_runtime.h>
#include <cuda_bf16.h>
#include <math.h>

// ---------------------------------------------------------------------------
// Problem constants
// ---------------------------------------------------------------------------
#define BB     4
#define TT     2048
#define DM     256
#define DFF    1024
#define NH     4
#define DK     64
#define BT     (BB*TT)          // 8192 rows

// ---------------------------------------------------------------------------
// Scratch
// ---------------------------------------------------------------------------
__device__ __nv_bfloat16 gb_h   [BT*DM];
__device__ __nv_bfloat16 gb_q   [BT*DM];
__device__ __nv_bfloat16 gb_k   [BT*DM];
__device__ __nv_bfloat16 gb_v   [BT*DM];
__device__ __nv_bfloat16 gb_attn[BT*DM];
__device__ __nv_bfloat16 gb_hf  [BT*DM];
__device__ __nv_bfloat16 gb_gate[BT*DFF];
__device__ float         g_x1   [BT*DM];
// bf16 weights
__device__ __nv_bfloat16 gb_wq[DM*DM];
__device__ __nv_bfloat16 gb_wk[DM*DM];
__device__ __nv_bfloat16 gb_wv[DM*DM];
__device__ __nv_bfloat16 gb_wo[DM*DM];
__device__ __nv_bfloat16 gb_wg[DFF*DM];
__device__ __nv_bfloat16 gb_wu[DFF*DM];
__device__ __nv_bfloat16 gb_wd[DM*DFF];

// ---------------------------------------------------------------------------
// helpers
// ---------------------------------------------------------------------------
__device__ __forceinline__ void mma_bf16(float* c, const unsigned* a, const unsigned* b) {
    asm volatile(
        "mma.sync.aligned.m16n8k16.row.col.f32.bf16.bf16.f32 "
        "{%0,%1,%2,%3}, {%4,%5,%6,%7}, {%8,%9}, {%0,%1,%2,%3};\n"
        : "+f"(c[0]), "+f"(c[1]), "+f"(c[2]), "+f"(c[3])
        : "r"(a[0]), "r"(a[1]), "r"(a[2]), "r"(a[3]), "r"(b[0]), "r"(b[1]));
}

__device__ __forceinline__ void ldsm4(unsigned* r, const __nv_bfloat16* p) {
    unsigned a = (unsigned)__cvta_generic_to_shared(p);
    asm volatile("ldmatrix.sync.aligned.m8n8.x4.shared.b16 {%0,%1,%2,%3}, [%4];"
                 : "=r"(r[0]), "=r"(r[1]), "=r"(r[2]), "=r"(r[3]) : "r"(a));
}
__device__ __forceinline__ void ldsm4t(unsigned* r, const __nv_bfloat16* p) {
    unsigned a = (unsigned)__cvta_generic_to_shared(p);
    asm volatile("ldmatrix.sync.aligned.m8n8.x4.trans.shared.b16 {%0,%1,%2,%3}, [%4];"
                 : "=r"(r[0]), "=r"(r[1]), "=r"(r[2]), "=r"(r[3]) : "r"(a));
}

__device__ __forceinline__ unsigned pack_bf16(float lo, float hi) {
    unsigned r;
    asm("cvt.rn.bf16x2.f32 %0, %1, %2;" : "=r"(r) : "f"(hi), "f"(lo));
    return r;
}

__device__ __forceinline__ void cpa16(void* s, const void* g) {
    unsigned sa = (unsigned)__cvta_generic_to_shared(s);
    asm volatile("cp.async.cg.shared.global [%0], [%1], 16;" :: "r"(sa), "l"(g));
}
__device__ __forceinline__ void cp_commit() { asm volatile("cp.async.commit_group;"); }
template<int N> __device__ __forceinline__ void cp_wait() {
    asm volatile("cp.async.wait_group %0;" :: "n"(N));
}

// ---------------------------------------------------------------------------
// Weight conversion fp32 -> bf16 (4 tensors per launch; grid.y selects)
// ---------------------------------------------------------------------------
__global__ void conv4(const float* s0, const float* s1, const float* s2, const float* s3,
                      __nv_bfloat16* d0, __nv_bfloat16* d1, __nv_bfloat16* d2,
                      __nv_bfloat16* d3) {
    const float* s = (blockIdx.y == 0) ? s0 : (blockIdx.y == 1) ? s1 : (blockIdx.y == 2) ? s2 : s3;
    __nv_bfloat16* d = (blockIdx.y == 0) ? d0 : (blockIdx.y == 1) ? d1 : (blockIdx.y == 2) ? d2 : d3;
    int i = blockIdx.x*blockDim.x + threadIdx.x;
    float4 v = ((const float4*)s)[i];
    __nv_bfloat162* d2p = (__nv_bfloat162*)d;
    d2p[2*i]   = __floats2bfloat162_rn(v.x, v.y);
    d2p[2*i+1] = __floats2bfloat162_rn(v.z, v.w);
}

// ---------------------------------------------------------------------------
// RMSNorm -> bf16 out
// ---------------------------------------------------------------------------
__global__ void rmsnorm_kernel(__nv_bfloat16* __restrict__ out, const float* __restrict__ x,
                               const float* __restrict__ w) {
    int row = blockIdx.x;
    int tid = threadIdx.x;
    float vx = x[row*DM + tid];
    float ss = vx*vx;
    #pragma unroll
    for (int off = 16; off >= 1; off >>= 1) ss += __shfl_xor_sync(0xffffffffu, ss, off);
    __shared__ float ws[8];
    if ((tid & 31) == 0) ws[tid >> 5] = ss;
    __syncthreads();
    float tot = ws[0];
    #pragma unroll
    for (int i = 1; i < 8; ++i) tot += ws[i];
    float rinv = rsqrtf(tot * (1.0f/DM) + 1e-5f);
    out[row*DM + tid] = __float2bfloat16_rn(vx * rinv * w[tid]);
}

// ---------------------------------------------------------------------------
// bf16 tensor-core GEMM: C[M,N] = A[M,K] @ Bw[N,K]^T (+res if fp32 out)
// 128 x BN_ tile, BK=64, 3-stage cp.async, 8 warps (4x2), ldmatrix b16
// OBF: true -> bf16 output (no residual), false -> fp32 output (+res)
// ---------------------------------------------------------------------------
#define TSTR 72   // bf16 units per smem row (64 + 8 pad)

template<int BN_, bool OBF>
__global__ __launch_bounds__(256, 2)
void gemm_bf16(const __nv_bfloat16* __restrict__ A,
               const __nv_bfloat16* __restrict__ B0, const __nv_bfloat16* __restrict__ B1,
               const __nv_bfloat16* __restrict__ B2,
               void* __restrict__ C0, void* __restrict__ C1, void* __restrict__ C2,
               const float* __restrict__ res,
               int M, int N, int K) {
    constexpr int WN  = BN_/16;
    constexpr int ASZ = 128*TSTR;
    constexpr int BSZ = BN_*TSTR;
    extern __shared__ __nv_bfloat16 smb[];
    __nv_bfloat16* As = smb;                  // 3 stages
    __nv_bfloat16* Bs = smb + 3*ASZ;

    const __nv_bfloat16* Bw = (blockIdx.z == 0) ? B0 : (blockIdx.z == 1 ? B1 : B2);
    void*                C  = (blockIdx.z == 0) ? C0 : (blockIdx.z == 1 ? C1 : C2);

    const int tid = threadIdx.x, lane = tid & 31, wid = tid >> 5;
    const int wrow = wid >> 1, wcol = wid & 1;
    const int row0 = blockIdx.y * 128;
    const int col0 = blockIdx.x * BN_;

    const int aoff = ((lane & 7) + ((lane >> 3) & 1)*8)*TSTR + (lane >> 4)*8;
    const int boff = ((lane & 7) + (lane >> 4)*8)*TSTR + ((lane >> 3) & 1)*8;

    float acc[2][WN][4];
    #pragma unroll
    for (int i = 0; i < 2; ++i)
        #pragma unroll
        for (int j = 0; j < WN; ++j)
            #pragma unroll
            for (int t = 0; t < 4; ++t) acc[i][j][t] = 0.f;

    auto load_stage = [&](int k0, int st) {
        __nv_bfloat16* as = As + st*ASZ;
        __nv_bfloat16* bs = Bs + st*BSZ;
        #pragma unroll
        for (int it = 0; it < 4; ++it) {
            int idx = it*256 + tid, r = idx >> 3, c8 = (idx & 7)*8;
            cpa16(as + r*TSTR + c8, A + (size_t)(row0 + r)*K + k0 + c8);
        }
        #pragma unroll
        for (int it = 0; it < BN_/32; ++it) {
            int idx = it*256 + tid, r = idx >> 3, c8 = (idx & 7)*8;
            cpa16(bs + r*TSTR + c8, Bw + (size_t)(col0 + r)*K + k0 + c8);
        }
        cp_commit();
    };

    const int nt = K / 64;
    load_stage(0, 0);
    load_stage(64, 1);
    for (int t = 0; t < nt; ++t) {
        if (t + 2 < nt)      { load_stage((t+2)*64, (t+2) % 3); cp_wait<2>(); }
        else if (t + 1 < nt) { cp_wait<1>(); }
        else                 { cp_wait<0>(); }
        __syncthreads();
        const __nv_bfloat16* as = As + (t % 3)*ASZ + aoff + wrow*32*TSTR;
        const __nv_bfloat16* bs = Bs + (t % 3)*BSZ + boff + wcol*(BN_/2)*TSTR;
        #pragma unroll
        for (int ks = 0; ks < 4; ++ks) {
            const int kk = ks*16;
            unsigned a[2][4], b[WN][2];
            #pragma unroll
            for (int i = 0; i < 2; ++i)
                ldsm4(a[i], as + i*16*TSTR + kk);
            #pragma unroll
            for (int jp = 0; jp < WN/2; ++jp)
                ldsm4(&b[2*jp][0], bs + jp*16*TSTR + kk);
            #pragma unroll
            for (int i = 0; i < 2; ++i)
                #pragma unroll
                for (int j = 0; j < WN; ++j)
                    mma_bf16(acc[i][j], a[i], b[j]);
        }
        __syncthreads();
    }

    #pragma unroll
    for (int i = 0; i < 2; ++i) {
        int r = row0 + wrow*32 + i*16 + (lane >> 2);
        #pragma unroll
        for (int j = 0; j < WN; ++j) {
            int c = col0 + wcol*(BN_/2) + j*8 + (lane & 3)*2;
            if (OBF) {
                __nv_bfloat16* Cb = (__nv_bfloat16*)C;
                *(unsigned*)(Cb + (size_t)r*N + c)     = pack_bf16(acc[i][j][0], acc[i][j][1]);
                *(unsigned*)(Cb + (size_t)(r+8)*N + c) = pack_bf16(acc[i][j][2], acc[i][j][3]);
            } else {
                float* Cf = (float*)C;
                float2 v01 = { acc[i][j][0], acc[i][j][1] };
                float2 v23 = { acc[i][j][2], acc[i][j][3] };
                if (res) {
                    float2 r01 = *(const float2*)(res + (size_t)r*N + c);
                    float2 r23 = *(const float2*)(res + (size_t)(r+8)*N + c);
                    v01.x += r01.x; v01.y += r01.y;
                    v23.x += r23.x; v23.y += r23.y;
                }
                *(float2*)(Cf + (size_t)r*N + c)     = v01;
                *(float2*)(Cf + (size_t)(r+8)*N + c) = v23;
            }
        }
    }
}

// ---------------------------------------------------------------------------
// Fused gate/up GEMM + SiLU (bf16): g = silu(A@Wg^T) * (A@Wu^T), bf16 out
// ---------------------------------------------------------------------------
__global__ __launch_bounds__(256, 2)
void gemm_gateup(const __nv_bfloat16* __restrict__ A,
                 const __nv_bfloat16* __restrict__ Wg, const __nv_bfloat16* __restrict__ Wu,
                 __nv_bfloat16* __restrict__ G, int M, int N, int K) {
    constexpr int ASZ = 128*TSTR;
    constexpr int BSZ = 64*TSTR;
    extern __shared__ __nv_bfloat16 smb[];
    __nv_bfloat16* As = smb;
    __nv_bfloat16* Gs = smb + 3*ASZ;
    __nv_bfloat16* Us = Gs + 3*BSZ;

    const int tid = threadIdx.x, lane = tid & 31, wid = tid >> 5;
    const int wrow = wid >> 1, wcol = wid & 1;
    const int row0 = blockIdx.y * 128;
    const int col0 = blockIdx.x * 64;

    const int aoff = ((lane & 7) + ((lane >> 3) & 1)*8)*TSTR + (lane >> 4)*8;
    const int boff = ((lane & 7) + (lane >> 4)*8)*TSTR + ((lane >> 3) & 1)*8;

    float accg[2][4][4], accu[2][4][4];
    #pragma unroll
    for (int i = 0; i < 2; ++i)
        #pragma unroll
        for (int j = 0; j < 4; ++j)
            #pragma unroll
            for (int t = 0; t < 4; ++t) { accg[i][j][t] = 0.f; accu[i][j][t] = 0.f; }

    auto load_stage = [&](int k0, int st) {
        __nv_bfloat16* as = As + st*ASZ;
        __nv_bfloat16* gs = Gs + st*BSZ;
        __nv_bfloat16* us = Us + st*BSZ;
        #pragma unroll
        for (int it = 0; it < 4; ++it) {
            int idx = it*256 + tid, r = idx >> 3, c8 = (idx & 7)*8;
            cpa16(as + r*TSTR + c8, A + (size_t)(row0 + r)*K + k0 + c8);
        }
        #pragma unroll
        for (int it = 0; it < 2; ++it) {
            int idx = it*256 + tid, r = idx >> 3, c8 = (idx & 7)*8;
            cpa16(gs + r*TSTR + c8, Wg + (size_t)(col0 + r)*K + k0 + c8);
            cpa16(us + r*TSTR + c8, Wu + (size_t)(col0 + r)*K + k0 + c8);
        }
        cp_commit();
    };

    const int nt = K / 64;
    load_stage(0, 0);
    load_stage(64, 1);
    for (int t = 0; t < nt; ++t) {
        if (t + 2 < nt)      { load_stage((t+2)*64, (t+2) % 3); cp_wait<2>(); }
        else if (t + 1 < nt) { cp_wait<1>(); }
        else                 { cp_wait<0>(); }
        __syncthreads();
        const __nv_bfloat16* as = As + (t % 3)*ASZ + aoff + wrow*32*TSTR;
        const __nv_bfloat16* gs = Gs + (t % 3)*BSZ + boff + wcol*32*TSTR;
        const __nv_bfloat16* us = Us + (t % 3)*BSZ + boff + wcol*32*TSTR;
        #pragma unroll
        for (int ks = 0; ks < 4; ++ks) {
            const int kk = ks*16;
            unsigned a[2][4], bg[4][2], bu[4][2];
            #pragma unroll
            for (int i = 0; i < 2; ++i)
                ldsm4(a[i], as + i*16*TSTR + kk);
            #pragma unroll
            for (int jp = 0; jp < 2; ++jp) {
                ldsm4(&bg[2*jp][0], gs + jp*16*TSTR + kk);
                ldsm4(&bu[2*jp][0], us + jp*16*TSTR + kk);
            }
            #pragma unroll
            for (int i = 0; i < 2; ++i)
                #pragma unroll
                for (int j = 0; j < 4; ++j) {
                    mma_bf16(accg[i][j], a[i], bg[j]);
                    mma_bf16(accu[i][j], a[i], bu[j]);
                }
        }
        __syncthreads();
    }

    #pragma unroll
    for (int i = 0; i < 2; ++i) {
        int r = row0 + wrow*32 + i*16 + (lane >> 2);
        #pragma unroll
        for (int j = 0; j < 4; ++j) {
            int c = col0 + wcol*32 + j*8 + (lane & 3)*2;
            float g0 = accg[i][j][0], g1 = accg[i][j][1];
            float g2 = accg[i][j][2], g3 = accg[i][j][3];
            float p0 = g0 / (1.f + __expf(-g0)) * accu[i][j][0];
            float p1 = g1 / (1.f + __expf(-g1)) * accu[i][j][1];
            float p2 = g2 / (1.f + __expf(-g2)) * accu[i][j][2];
            float p3 = g3 / (1.f + __expf(-g3)) * accu[i][j][3];
            *(unsigned*)(G + (size_t)r*N + c)     = pack_bf16(p0, p1);
            *(unsigned*)(G + (size_t)(r+8)*N + c) = pack_bf16(p2, p3);
        }
    }
}

// ---------------------------------------------------------------------------
// bf16 tensor-core flash attention, double-buffered K/V, occ 4
// 512 blocks (16 bh x 32 q-tiles of 64 rows, heavy-first), 128 threads
// ---------------------------------------------------------------------------
#define QSTR 72
#define KSTR 72
#define VSTR 72

__global__ __launch_bounds__(128, 4)
void attn_bf16(__nv_bfloat16* __restrict__ out, const __nv_bfloat16* __restrict__ q,
               const __nv_bfloat16* __restrict__ k, const __nv_bfloat16* __restrict__ v) {
    extern __shared__ __nv_bfloat16 smb[];
    __nv_bfloat16* Qs = smb;                    // 64 x QSTR
    __nv_bfloat16* Ks = Qs + 64*QSTR;           // 2 stages 64 x KSTR
    __nv_bfloat16* Vs = Ks + 2*64*KSTR;         // 2 stages 64 x VSTR

    const int tid = threadIdx.x, lane = tid & 31, wid = tid >> 5;
    const int bh = blockIdx.x;
    const int qx = 31 - blockIdx.y;             // heavy tiles first
    const int b = bh >> 2, h = bh & 3;
    const int q0 = qx * 64;
    const int ntile = qx + 1;
    const size_t base = (size_t)b*TT*DM + (size_t)h*DK;

    const int r0l = wid*16 + (lane >> 2);
    const float sc = 0.125f;

    // ldmatrix lane offsets (A-pattern also serves V-trans)
    const int aoff = ((lane & 7) + ((lane >> 3) & 1)*8)*QSTR + (lane >> 4)*8;
    const int koff = ((lane & 7) + (lane >> 4)*8)*KSTR + ((lane >> 3) & 1)*8;
    const int voff = ((lane & 7) + ((lane >> 3) & 1)*8)*VSTR + (lane >> 4)*8;

    auto load_kv = [&](int jt, int st) {
        const int k0 = jt*64;
        __nv_bfloat16* ks_ = Ks + st*64*KSTR;
        __nv_bfloat16* vs_ = Vs + st*64*VSTR;
        #pragma unroll
        for (int it = 0; it < 4; ++it) {
            int idx = it*128 + tid, r = idx >> 3, c8 = (idx & 7)*8;
            cpa16(ks_ + r*KSTR + c8, k + base + (size_t)(k0 + r)*DM + c8);
            cpa16(vs_ + r*VSTR + c8, v + base + (size_t)(k0 + r)*DM + c8);
        }
        cp_commit();
    };

    // Q tile + first KV stage
    #pragma unroll
    for (int it = 0; it < 4; ++it) {
        int idx = it*128 + tid, r = idx >> 3, c8 = (idx & 7)*8;
        cpa16(Qs + r*QSTR + c8, q + base + (size_t)(q0 + r)*DM + c8);
    }
    cp_commit();
    load_kv(0, 0);

    float o[8][4];
    #pragma unroll
    for (int j = 0; j < 8; ++j)
        #pragma unroll
        for (int t = 0; t < 4; ++t) o[j][t] = 0.f;
    float m0 = -1e30f, m1 = -1e30f, l0 = 0.f, l1 = 0.f;

    for (int jt = 0; jt < ntile; ++jt) {
        if (jt + 1 < ntile) { load_kv(jt+1, (jt+1) & 1); cp_wait<1>(); }
        else                { cp_wait<0>(); }
        __syncthreads();
        const __nv_bfloat16* ks_ = Ks + (jt & 1)*64*KSTR;
        const __nv_bfloat16* vs_ = Vs + (jt & 1)*64*VSTR;
        const int k0 = jt*64;

        // ---- S = Q @ K^T : 4 k16 steps, 8 n-tiles ----
        float s[8][4];
        #pragma unroll
        for (int j = 0; j < 8; ++j)
            #pragma unroll
            for (int t = 0; t < 4; ++t) s[j][t] = 0.f;
        #pragma unroll
        for (int ks = 0; ks < 4; ++ks) {
            const int kk = ks*16;
            unsigned aq[4], bv[8][2];
            ldsm4(aq, Qs + wid*16*QSTR + aoff + kk);
            #pragma unroll
            for (int jp = 0; jp < 4; ++jp)
                ldsm4(&bv[2*jp][0], ks_ + jp*16*KSTR + koff + kk);
            #pragma unroll
            for (int j = 0; j < 8; ++j)
                mma_bf16(s[j], aq, bv[j]);
        }

        // ---- causal mask (diagonal tile only) ----
        if (jt == ntile - 1) {
            const int row_a = q0 + r0l, row_b = row_a + 8;
            #pragma unroll
            for (int j = 0; j < 8; ++j) {
                int col = k0 + j*8 + 2*(lane & 3);
                if (col     > row_a) s[j][0] = -1e30f;
                if (col + 1 > row_a) s[j][1] = -1e30f;
                if (col     > row_b) s[j][2] = -1e30f;
                if (col + 1 > row_b) s[j][3] = -1e30f;
            }
        }

        // ---- online softmax ----
        float mx0 = -1e30f, mx1 = -1e30f;
        #pragma unroll
        for (int j = 0; j < 8; ++j) {
            mx0 = fmaxf(mx0, fmaxf(s[j][0], s[j][1]));
            mx1 = fmaxf(mx1, fmaxf(s[j][2], s[j][3]));
        }
        #pragma unroll
        for (int off = 1; off <= 2; off <<= 1) {
            mx0 = fmaxf(mx0, __shfl_xor_sync(0xffffffffu, mx0, off));
            mx1 = fmaxf(mx1, __shfl_xor_sync(0xffffffffu, mx1, off));
        }
        float mn0 = fmaxf(m0, mx0), mn1 = fmaxf(m1, mx1);
        float al0 = __expf((m0 - mn0)*sc), al1 = __expf((m1 - mn1)*sc);
        m0 = mn0; m1 = mn1;
        float rs0 = 0.f, rs1 = 0.f;
        #pragma unroll
        for (int j = 0; j < 8; ++j) {
            s[j][0] = __expf((s[j][0] - mn0)*sc); rs0 += s[j][0];
            s[j][1] = __expf((s[j][1] - mn0)*sc); rs0 += s[j][1];
            s[j][2] = __expf((s[j][2] - mn1)*sc); rs1 += s[j][2];
            s[j][3] = __expf((s[j][3] - mn1)*sc); rs1 += s[j][3];
        }
        #pragma unroll
        for (int off = 1; off <= 2; off <<= 1) {
            rs0 += __shfl_xor_sync(0xffffffffu, rs0, off);
            rs1 += __shfl_xor_sync(0xffffffffu, rs1, off);
        }
        l0 = l0*al0 + rs0;
        l1 = l1*al1 + rs1;

        // ---- O = O*alpha + P @ V (P packs directly to bf16 A-fragments) ----
        #pragma unroll
        for (int j = 0; j < 8; ++j) {
            o[j][0] *= al0; o[j][1] *= al0;
            o[j][2] *= al1; o[j][3] *= al1;
        }
        #pragma unroll
        for (int kb = 0; kb < 4; ++kb) {
            unsigned ap[4];
            ap[0] = pack_bf16(s[2*kb  ][0], s[2*kb  ][1]);
            ap[1] = pack_bf16(s[2*kb  ][2], s[2*kb  ][3]);
            ap[2] = pack_bf16(s[2*kb+1][0], s[2*kb+1][1]);
            ap[3] = pack_bf16(s[2*kb+1][2], s[2*kb+1][3]);
            const int kk = kb*16;
            unsigned bv[8][2];
            #pragma unroll
            for (int jp = 0; jp < 4; ++jp)
                ldsm4t(&bv[2*jp][0], vs_ + kk*VSTR + voff + jp*16);
            #pragma unroll
            for (int j = 0; j < 8; ++j)
                mma_bf16(o[j], ap, bv[j]);
        }
        __syncthreads();                // all reads of this stage done
    }

    // ---- epilogue (bf16 out) ----
    const float inv0 = 1.f / l0, inv1 = 1.f / l1;
    const int grow = q0 + r0l;
    #pragma unroll
    for (int j = 0; j < 8; ++j) {
        int cc = j*8 + 2*(lane & 3);
        *(unsigned*)(out + base + (size_t)grow*DM + cc) =
            pack_bf16(o[j][0]*inv0, o[j][1]*inv0);
        *(unsigned*)(out + base + (size_t)(grow + 8)*DM + cc) =
            pack_bf16(o[j][2]*inv1, o[j][3]*inv1);
    }
}

// ---------------------------------------------------------------------------
// Launch
// ---------------------------------------------------------------------------
extern "C" void kernel_launch(void* const* d_in, const int* in_sizes, int n_in,
                              void* d_out, int out_size) {
    const float* x        = (const float*)d_in[0];
    const float* rms_attn = (const float*)d_in[2];
    const float* wq       = (const float*)d_in[3];
    const float* wk       = (const float*)d_in[4];
    const float* wv       = (const float*)d_in[5];
    const float* wo       = (const float*)d_in[6];
    const float* rms_ffn  = (const float*)d_in[7];
    const float* w_gate   = (const float*)d_in[8];
    const float* w_up     = (const float*)d_in[9];
    const float* w_down   = (const float*)d_in[10];
    float* out = (float*)d_out;

    __nv_bfloat16 *h, *q, *k, *v, *attn, *hf, *gate;
    __nv_bfloat16 *bwq, *bwk, *bwv, *bwo, *bwg, *bwu, *bwd;
    float *x1;
    cudaGetSymbolAddress((void**)&h,    gb_h);
    cudaGetSymbolAddress((void**)&q,    gb_q);
    cudaGetSymbolAddress((void**)&k,    gb_k);
    cudaGetSymbolAddress((void**)&v,    gb_v);
    cudaGetSymbolAddress((void**)&attn, gb_attn);
    cudaGetSymbolAddress((void**)&hf,   gb_hf);
    cudaGetSymbolAddress((void**)&gate, gb_gate);
    cudaGetSymbolAddress((void**)&x1,   g_x1);
    cudaGetSymbolAddress((void**)&bwq,  gb_wq);
    cudaGetSymbolAddress((void**)&bwk,  gb_wk);
    cudaGetSymbolAddress((void**)&bwv,  gb_wv);
    cudaGetSymbolAddress((void**)&bwo,  gb_wo);
    cudaGetSymbolAddress((void**)&bwg,  gb_wg);
    cudaGetSymbolAddress((void**)&bwu,  gb_wu);
    cudaGetSymbolAddress((void**)&bwd,  gb_wd);

    const int GS128 = 3*(128 + 128)*TSTR*2;                 // 110592 B
    const int GS64  = 3*(128 +  64)*TSTR*2;                 // 82944 B
    const int GSGU  = 3*(128 + 64 + 64)*TSTR*2;             // 110592 B
    const int ASM   = (64*QSTR + 2*64*KSTR + 2*64*VSTR)*2;  // 46080 B
    cudaFuncSetAttribute((const void*)gemm_bf16<128,true>,  cudaFuncAttributeMaxDynamicSharedMemorySize, GS128);
    cudaFuncSetAttribute((const void*)gemm_bf16<64,false>,  cudaFuncAttributeMaxDynamicSharedMemorySize, GS64);
    cudaFuncSetAttribute((const void*)gemm_gateup,          cudaFuncAttributeMaxDynamicSharedMemorySize, GSGU);
    cudaFuncSetAttribute((const void*)attn_bf16,            cudaFuncAttributeMaxDynamicSharedMemorySize, ASM);

    // 0. convert weights to bf16
    conv4<<<dim3(DM*DM/1024, 4), 256>>>(wq, wk, wv, wo, bwq, bwk, bwv, bwo);
    conv4<<<dim3(DFF*DM/1024, 3), 256>>>(w_gate, w_up, w_down, w_down, bwg, bwu, bwd, bwd);

    // 1. h = rmsnorm(x) -> bf16
    rmsnorm_kernel<<<BT, 256>>>(h, x, rms_attn);

    // 2. fused q,k,v projections -> bf16
    gemm_bf16<128,true><<<dim3(DM/128, BT/128, 3), 256, GS128>>>(
        h, bwq, bwk, bwv, q, k, v, nullptr, BT, DM, DM);

    // 3. attention -> bf16
    attn_bf16<<<dim3(BB*NH, 32), 128, ASM>>>(attn, q, k, v);

    // 4. x1 = x + attn @ wo^T  (fp32)
    gemm_bf16<64,false><<<dim3(DM/64, BT/128, 1), 256, GS64>>>(
        attn, bwo, bwo, bwo, x1, x1, x1, x, BT, DM, DM);

    // 5. hf = rmsnorm(x1) -> bf16
    rmsnorm_kernel<<<BT, 256>>>(hf, x1, rms_ffn);

    // 6. fused gate/up/silu -> bf16
    gemm_gateup<<<dim3(DFF/64, BT/128), 256, GSGU>>>(
        hf, bwg, bwu, gate, BT, DFF, DM);

    // 7. out = x1 + gate @ w_down^T  (fp32)
    gemm_bf16<64,false><<<dim3(DM/64, BT/128, 1), 256, GS64>>>(
        gate, bwd, bwd, bwd, out, out, out, x1, BT, DM, DFF);
}